// round 7
// baseline (speedup 1.0000x reference)
#include <cuda_runtime.h>
#include <cstdint>

// Problem constants
constexpr int S_LEN = 4096;
constexpr int DM    = 1024;
constexpr int NH    = 16;
constexpr int HD    = 64;
constexpr int QKV_N = 3 * DM;  // 3072

// Scratch device globals (allocation-free rule)
// All K-dimension data stored perm8-permuted (see below). V section of g_qkv
// and all GEMM outputs' n-dims are unpermuted.
__device__ float g_x   [(size_t)S_LEN * DM];
__device__ float g_wqkv[(size_t)QKV_N * DM];
__device__ float g_wout[(size_t)DM * DM];
__device__ float g_qkv [(size_t)S_LEN * QKV_N];  // q sec pre-scaled by 0.125; q,k head-dim permuted
__device__ float g_att [(size_t)S_LEN * DM];     // model-dim permuted

// ---------------------------------------------------------------------------
// perm8: within each 8-element k-group, slot(j) = 2j (j<4) else 2(j-4)+1.
// Makes fragment pairs (k, k+4) adjacent -> LDS.64 fragment loads.
// ---------------------------------------------------------------------------
__host__ __device__ __forceinline__ int perm8(int c) {
    int j = c & 7;
    int s = (j < 4) ? (2 * j) : (2 * (j - 4) + 1);
    return (c & ~7) | s;
}

// ---------------------------------------------------------------------------
// Helpers
// ---------------------------------------------------------------------------
__device__ __forceinline__ float tf32r(float x) {
    uint32_t u;
    asm("cvt.rna.tf32.f32 %0, %1;" : "=r"(u) : "f"(x));
    return __uint_as_float(u);
}

__device__ __forceinline__ void cp_async16(void* smem_dst, const void* gmem_src) {
    uint32_t s = (uint32_t)__cvta_generic_to_shared(smem_dst);
    asm volatile("cp.async.cg.shared.global [%0], [%1], 16;" :: "r"(s), "l"(gmem_src));
}
__device__ __forceinline__ void cp_commit() {
    asm volatile("cp.async.commit_group;");
}
template<int N>
__device__ __forceinline__ void cp_wait() {
    asm volatile("cp.async.wait_group %0;" :: "n"(N));
}

// m16n8k8 tf32 mma: D += A*B.
__device__ __forceinline__ void mma_tf32(float c[4], const float a[4],
                                         float b0, float b1) {
    asm volatile(
        "mma.sync.aligned.m16n8k8.row.col.f32.tf32.tf32.f32 "
        "{%0,%1,%2,%3}, {%4,%5,%6,%7}, {%8,%9}, {%0,%1,%2,%3};"
        : "+f"(c[0]), "+f"(c[1]), "+f"(c[2]), "+f"(c[3])
        : "r"(__float_as_uint(a[0])), "r"(__float_as_uint(a[1])),
          "r"(__float_as_uint(a[2])), "r"(__float_as_uint(a[3])),
          "r"(__float_as_uint(b0)),  "r"(__float_as_uint(b1)));
}

// ---------------------------------------------------------------------------
// Elementwise tf32 rounding pre-pass with perm8 scatter on the flat index.
// (All array row strides are %8==0 so flat-index perm == column perm.)
// ---------------------------------------------------------------------------
__global__ void cvt_tf32_kernel(const float* __restrict__ in,
                                float* __restrict__ out, int n4) {
    int i = blockIdx.x * blockDim.x + threadIdx.x;
    if (i < n4) {
        float4 v = ((const float4*)in)[i];
        int base = i * 4;
        out[perm8(base + 0)] = tf32r(v.x);
        out[perm8(base + 1)] = tf32r(v.y);
        out[perm8(base + 2)] = tf32r(v.z);
        out[perm8(base + 3)] = tf32r(v.w);
    }
}

// ---------------------------------------------------------------------------
// TF32 GEMM: C[M,N] = A[M,K] * B[N,K]^T, A/B k-permuted. Block 128x128x32,
// 256 threads, 3-stage cp.async pipeline, one __syncthreads per K-iter.
// Fragment loads are LDS.64 (k-pairs adjacent).
// MODE 1: round output to tf32; permute output cols < 2*DM (q,k head-dims);
//         pre-scale q columns (n0 < DM) by 0.125.
// MODE 0: plain fp32 output, unpermuted.
// ---------------------------------------------------------------------------
constexpr int GSTG = 3;
constexpr int GEMM_SMEM = GSTG * 2 * 128 * 36 * (int)sizeof(float);  // 110592

template<int MODE>
__global__ __launch_bounds__(256, 2) void gemm_tf32(
    const float* __restrict__ A, const float* __restrict__ B,
    float* __restrict__ C, int M, int N, int K)
{
    extern __shared__ float sm[];
    float* AsBase = sm;
    float* BsBase = sm + GSTG * 128 * 36;

    const int tid  = threadIdx.x;
    const int lane = tid & 31;
    const int wid  = tid >> 5;
    const int wm   = (wid >> 2) * 64;
    const int wn   = (wid & 3) * 32;
    const int m0   = blockIdx.y * 128;
    const int n0   = blockIdx.x * 128;

    const int ldr = tid >> 3;
    const int ldc = (tid & 7) * 4;

    const int NI = K / 32;

    auto issue_tile = [&](int it, int buf) {
        const float* Ag = A + (size_t)m0 * K + it * 32;
        const float* Bg = B + (size_t)n0 * K + it * 32;
        float* As = AsBase + buf * (128 * 36);
        float* Bs = BsBase + buf * (128 * 36);
#pragma unroll
        for (int p = 0; p < 4; ++p) {
            int row = p * 32 + ldr;
            cp_async16(&As[row * 36 + ldc], &Ag[(size_t)row * K + ldc]);
            cp_async16(&Bs[row * 36 + ldc], &Bg[(size_t)row * K + ldc]);
        }
        cp_commit();
    };

    float acc[4][4][4];
#pragma unroll
    for (int i = 0; i < 4; ++i)
#pragma unroll
        for (int j = 0; j < 4; ++j)
#pragma unroll
            for (int c = 0; c < 4; ++c) acc[i][j][c] = 0.f;

    issue_tile(0, 0);
    issue_tile(1, 1);

    for (int it = 0; it < NI; ++it) {
        if (it + 1 < NI) cp_wait<1>(); else cp_wait<0>();
        __syncthreads();
        if (it + 2 < NI) issue_tile(it + 2, (it + 2) % GSTG);

        const float* As = AsBase + (it % GSTG) * (128 * 36);
        const float* Bs = BsBase + (it % GSTG) * (128 * 36);

#pragma unroll
        for (int kk = 0; kk < 4; ++kk) {
            const int kb2 = kk * 8 + 2 * (lane & 3);   // permuted slot base
            float a[4][4];
#pragma unroll
            for (int mt = 0; mt < 4; ++mt) {
                int r = wm + mt * 16 + (lane >> 2);
                float2 lo = *(const float2*)&As[r * 36 + kb2];
                float2 hi = *(const float2*)&As[(r + 8) * 36 + kb2];
                a[mt][0] = lo.x; a[mt][2] = lo.y;
                a[mt][1] = hi.x; a[mt][3] = hi.y;
            }
#pragma unroll
            for (int nt = 0; nt < 4; ++nt) {
                int cI = wn + nt * 8 + (lane >> 2);
                float2 b = *(const float2*)&Bs[cI * 36 + kb2];
#pragma unroll
                for (int mt = 0; mt < 4; ++mt)
                    mma_tf32(acc[mt][nt], a[mt], b.x, b.y);
            }
        }
    }

    const float oscale = (MODE == 1 && n0 < DM) ? 0.125f : 1.0f;
#pragma unroll
    for (int mt = 0; mt < 4; ++mt) {
#pragma unroll
        for (int nt = 0; nt < 4; ++nt) {
            int row = m0 + wm + mt * 16 + (lane >> 2);
            int col = n0 + wn + nt * 8 + 2 * (lane & 3);
            float v0 = acc[mt][nt][0] * oscale, v1 = acc[mt][nt][1] * oscale;
            float v2 = acc[mt][nt][2] * oscale, v3 = acc[mt][nt][3] * oscale;
            if (MODE == 1) {
                v0 = tf32r(v0); v1 = tf32r(v1); v2 = tf32r(v2); v3 = tf32r(v3);
                if (col < 2 * DM) {   // q,k sections: head-dim permuted
                    int c0 = perm8(col), c1 = perm8(col + 1);
                    C[(size_t)row * N + c0]       = v0;
                    C[(size_t)row * N + c1]       = v1;
                    C[(size_t)(row + 8) * N + c0] = v2;
                    C[(size_t)(row + 8) * N + c1] = v3;
                    continue;
                }
            }
            *(float2*)&C[(size_t)row * N + col]       = make_float2(v0, v1);
            *(float2*)&C[(size_t)(row + 8) * N + col] = make_float2(v2, v3);
        }
    }
}

// ---------------------------------------------------------------------------
// Flash attention (tf32 mma, causal). Block = (64-row Q tile, head).
// 128 threads / 4 warps. 2-stage KV pipeline, one __syncthreads per KV tile.
// Q/K head-dims and Ps cols are permuted -> LDS.64 fragments; V unpermuted.
// ---------------------------------------------------------------------------
constexpr int FL_SMEM = (2 * 64 * 68 + 2 * 64 * 68 + 2 * 64 * 72) * (int)sizeof(float);

__global__ __launch_bounds__(128) void flash_tf32(
    const float* __restrict__ qkv, float* __restrict__ out)
{
    extern __shared__ float sm[];
    float* Qs  = sm;
    float* Ps  = Qs + 64 * 68;
    float* KsB = Ps + 64 * 68;
    float* VsB = KsB + 2 * 64 * 68;

    const int tid  = threadIdx.x;
    const int lane = tid & 31;
    const int w    = tid >> 5;
    const int h    = blockIdx.y;
    const int qt   = (int)gridDim.x - 1 - (int)blockIdx.x;
    const int q0   = qt * 64;

    const int ldr = tid >> 4;
    const int ldc = (tid & 15) * 4;

    const float* qg = qkv + (size_t)q0 * QKV_N + h * HD;

    auto issue_kv = [&](int t, int buf) {
        const float* kg = qkv + (size_t)(t * 64) * QKV_N + DM + h * HD;
        const float* vg = kg + DM;
        float* Ks = KsB + buf * (64 * 68);
        float* Vs = VsB + buf * (64 * 72);
#pragma unroll
        for (int p = 0; p < 8; ++p) {
            int row = p * 8 + ldr;
            cp_async16(&Ks[row * 68 + ldc], &kg[(size_t)row * QKV_N + ldc]);
            cp_async16(&Vs[row * 72 + ldc], &vg[(size_t)row * QKV_N + ldc]);
        }
        cp_commit();
    };

    {
#pragma unroll
        for (int p = 0; p < 8; ++p) {
            int row = p * 8 + ldr;
            cp_async16(&Qs[row * 68 + ldc], &qg[(size_t)row * QKV_N + ldc]);
        }
    }
    issue_kv(0, 0);

    const int r  = (lane >> 2);
    const int qr = w * 16 + r;
    float m_i[2] = {-1e30f, -1e30f};
    float l_i[2] = {0.f, 0.f};
    float oacc[8][4];
#pragma unroll
    for (int n = 0; n < 8; ++n)
#pragma unroll
        for (int c = 0; c < 4; ++c) oacc[n][c] = 0.f;

    for (int t = 0; t <= qt; ++t) {
        cp_wait<0>();
        __syncthreads();
        if (t + 1 <= qt) issue_kv(t + 1, (t + 1) & 1);

        const float* Ks = KsB + (t & 1) * (64 * 68);
        const float* Vs = VsB + (t & 1) * (64 * 72);

        float sacc[8][4];
#pragma unroll
        for (int n = 0; n < 8; ++n)
#pragma unroll
            for (int c = 0; c < 4; ++c) sacc[n][c] = 0.f;

        // S = Q K^T  (Q pre-scaled; Q/K head-dim permuted -> LDS.64 pairs)
#pragma unroll
        for (int kt = 0; kt < 8; ++kt) {
            const int kb2 = kt * 8 + 2 * (lane & 3);
            float a[4];
            {
                float2 lo = *(const float2*)&Qs[qr * 68 + kb2];
                float2 hi = *(const float2*)&Qs[(qr + 8) * 68 + kb2];
                a[0] = lo.x; a[2] = lo.y; a[1] = hi.x; a[3] = hi.y;
            }
#pragma unroll
            for (int nt = 0; nt < 8; ++nt) {
                int cI = nt * 8 + (lane >> 2);
                float2 b = *(const float2*)&Ks[cI * 68 + kb2];
                mma_tf32(sacc[nt], a, b.x, b.y);
            }
        }

        if (t == qt) {
#pragma unroll
            for (int nt = 0; nt < 8; ++nt) {
#pragma unroll
                for (int c = 0; c < 4; ++c) {
                    int col = nt * 8 + 2 * (lane & 3) + (c & 1);
                    int rowL = qr + (c >> 1) * 8;
                    if (col > rowL) sacc[nt][c] = -1e30f;
                }
            }
        }

        float alpha[2];
#pragma unroll
        for (int half = 0; half < 2; ++half) {
            float mx = -1e30f;
#pragma unroll
            for (int nt = 0; nt < 8; ++nt) {
                mx = fmaxf(mx, sacc[nt][half * 2]);
                mx = fmaxf(mx, sacc[nt][half * 2 + 1]);
            }
            mx = fmaxf(mx, __shfl_xor_sync(0xffffffffu, mx, 1, 4));
            mx = fmaxf(mx, __shfl_xor_sync(0xffffffffu, mx, 2, 4));
            float mnew = fmaxf(m_i[half], mx);
            alpha[half] = __expf(m_i[half] - mnew);
            m_i[half] = mnew;
            float rs = 0.f;
#pragma unroll
            for (int nt = 0; nt < 8; ++nt) {
                float p0 = __expf(sacc[nt][half * 2]     - mnew);
                float p1 = __expf(sacc[nt][half * 2 + 1] - mnew);
                sacc[nt][half * 2]     = p0;
                sacc[nt][half * 2 + 1] = p1;
                rs += p0 + p1;
            }
            rs += __shfl_xor_sync(0xffffffffu, rs, 1, 4);
            rs += __shfl_xor_sync(0xffffffffu, rs, 2, 4);
            l_i[half] = l_i[half] * alpha[half] + rs;
        }

#pragma unroll
        for (int nt = 0; nt < 8; ++nt) {
            oacc[nt][0] *= alpha[0]; oacc[nt][1] *= alpha[0];
            oacc[nt][2] *= alpha[1]; oacc[nt][3] *= alpha[1];
        }

        // Stage P (tf32-rounded) into Ps with permuted cols
#pragma unroll
        for (int nt = 0; nt < 8; ++nt) {
            int colb = nt * 8 + 2 * (lane & 3);
            int c0 = perm8(colb), c1 = perm8(colb + 1);
            Ps[qr * 68 + c0]       = tf32r(sacc[nt][0]);
            Ps[qr * 68 + c1]       = tf32r(sacc[nt][1]);
            Ps[(qr + 8) * 68 + c0] = tf32r(sacc[nt][2]);
            Ps[(qr + 8) * 68 + c1] = tf32r(sacc[nt][3]);
        }
        __syncwarp();

        // O += P V  (P permuted -> LDS.64 pairs; V rows unpermuted)
#pragma unroll
        for (int kt = 0; kt < 8; ++kt) {
            const int kb2 = kt * 8 + 2 * (lane & 3);   // P slot base
            const int kb  = kt * 8 + (lane & 3);       // V orig row
            float a[4];
            {
                float2 lo = *(const float2*)&Ps[qr * 68 + kb2];
                float2 hi = *(const float2*)&Ps[(qr + 8) * 68 + kb2];
                a[0] = lo.x; a[2] = lo.y; a[1] = hi.x; a[3] = hi.y;
            }
#pragma unroll
            for (int nt = 0; nt < 8; ++nt) {
                int dI = nt * 8 + (lane >> 2);
                float b0 = Vs[kb * 72 + dI];
                float b1 = Vs[(kb + 4) * 72 + dI];
                mma_tf32(oacc[nt], a, b0, b1);
            }
        }
    }

    // Epilogue: normalize, round, store g_att with model-dim permuted
    float inv0 = 1.f / l_i[0];
    float inv1 = 1.f / l_i[1];
#pragma unroll
    for (int nt = 0; nt < 8; ++nt) {
        int colb = h * HD + nt * 8 + 2 * (lane & 3);
        int c0 = perm8(colb), c1 = perm8(colb + 1);
        int row = q0 + qr;
        out[(size_t)row * DM + c0]       = tf32r(oacc[nt][0] * inv0);
        out[(size_t)row * DM + c1]       = tf32r(oacc[nt][1] * inv0);
        out[(size_t)(row + 8) * DM + c0] = tf32r(oacc[nt][2] * inv1);
        out[(size_t)(row + 8) * DM + c1] = tf32r(oacc[nt][3] * inv1);
    }
}

// ---------------------------------------------------------------------------
// Launch
// ---------------------------------------------------------------------------
extern "C" void kernel_launch(void* const* d_in, const int* in_sizes, int n_in,
                              void* d_out, int out_size)
{
    const float* x     = (const float*)d_in[0];
    const float* w_qkv = (const float*)d_in[1];
    const float* w_out = (const float*)d_in[2];
    float* out = (float*)d_out;

    float *xr, *wqkvr, *woutr, *qkvp, *attp;
    cudaGetSymbolAddress((void**)&xr,    g_x);
    cudaGetSymbolAddress((void**)&wqkvr, g_wqkv);
    cudaGetSymbolAddress((void**)&woutr, g_wout);
    cudaGetSymbolAddress((void**)&qkvp,  g_qkv);
    cudaGetSymbolAddress((void**)&attp,  g_att);

    cudaFuncSetAttribute(gemm_tf32<1>,
                         cudaFuncAttributeMaxDynamicSharedMemorySize, GEMM_SMEM);
    cudaFuncSetAttribute(gemm_tf32<0>,
                         cudaFuncAttributeMaxDynamicSharedMemorySize, GEMM_SMEM);
    cudaFuncSetAttribute(flash_tf32,
                         cudaFuncAttributeMaxDynamicSharedMemorySize, FL_SMEM);

    // 0) tf32-round + perm8 the inputs
    {
        int n4;
        n4 = S_LEN * DM / 4;
        cvt_tf32_kernel<<<(n4 + 255) / 256, 256>>>(x, xr, n4);
        n4 = QKV_N * DM / 4;
        cvt_tf32_kernel<<<(n4 + 255) / 256, 256>>>(w_qkv, wqkvr, n4);
        n4 = DM * DM / 4;
        cvt_tf32_kernel<<<(n4 + 255) / 256, 256>>>(w_out, woutr, n4);
    }
    // 1) QKV projection (rounds output; permutes q,k head-dims; scales q)
    {
        dim3 grid(QKV_N / 128, S_LEN / 128);
        gemm_tf32<1><<<grid, 256, GEMM_SMEM>>>(xr, wqkvr, qkvp, S_LEN, QKV_N, DM);
    }
    // 2) Flash attention
    {
        dim3 grid(S_LEN / 64, NH);
        flash_tf32<<<grid, 128, FL_SMEM>>>(qkvp, attp);
    }
    // 3) Output projection (unpermuted fp32 output)
    {
        dim3 grid(DM / 128, S_LEN / 128);
        gemm_tf32<0><<<grid, 256, GEMM_SMEM>>>(attp, woutr, out, S_LEN, DM, DM);
    }
}

// round 8
// speedup vs baseline: 2.4288x; 2.4288x over previous
#include <cuda_runtime.h>
#include <cuda_fp16.h>
#include <cstdint>

// Problem constants
constexpr int S_LEN = 4096;
constexpr int DM    = 1024;
constexpr int NH    = 16;
constexpr int HD    = 64;
constexpr int QKV_N = 3 * DM;  // 3072

// Scratch device globals (allocation-free rule) — all fp16
__device__ __half g_x   [(size_t)S_LEN * DM];
__device__ __half g_wqkv[(size_t)QKV_N * DM];
__device__ __half g_wout[(size_t)DM * DM];
__device__ __half g_qkv [(size_t)S_LEN * QKV_N];  // q section pre-scaled by 0.125
__device__ __half g_att [(size_t)S_LEN * DM];

// ---------------------------------------------------------------------------
// Helpers
// ---------------------------------------------------------------------------
__device__ __forceinline__ void cp_async16(void* smem_dst, const void* gmem_src) {
    uint32_t s = (uint32_t)__cvta_generic_to_shared(smem_dst);
    asm volatile("cp.async.cg.shared.global [%0], [%1], 16;" :: "r"(s), "l"(gmem_src));
}
__device__ __forceinline__ void cp_commit() {
    asm volatile("cp.async.commit_group;");
}
template<int N>
__device__ __forceinline__ void cp_wait() {
    asm volatile("cp.async.wait_group %0;" :: "n"(N));
}
__device__ __forceinline__ uint32_t smem_u32(const void* p) {
    return (uint32_t)__cvta_generic_to_shared(p);
}

__device__ __forceinline__ void ldmx4(uint32_t r[4], uint32_t a) {
    asm volatile("ldmatrix.sync.aligned.m8n8.x4.shared.b16 {%0,%1,%2,%3}, [%4];"
                 : "=r"(r[0]), "=r"(r[1]), "=r"(r[2]), "=r"(r[3]) : "r"(a));
}
__device__ __forceinline__ void ldmx4t(uint32_t r[4], uint32_t a) {
    asm volatile("ldmatrix.sync.aligned.m8n8.x4.trans.shared.b16 {%0,%1,%2,%3}, [%4];"
                 : "=r"(r[0]), "=r"(r[1]), "=r"(r[2]), "=r"(r[3]) : "r"(a));
}

// m16n8k16 fp16 mma, fp32 accumulate
__device__ __forceinline__ void mma_f16(float c[4], const uint32_t a[4],
                                        uint32_t b0, uint32_t b1) {
    asm volatile(
        "mma.sync.aligned.m16n8k16.row.col.f32.f16.f16.f32 "
        "{%0,%1,%2,%3}, {%4,%5,%6,%7}, {%8,%9}, {%0,%1,%2,%3};"
        : "+f"(c[0]), "+f"(c[1]), "+f"(c[2]), "+f"(c[3])
        : "r"(a[0]), "r"(a[1]), "r"(a[2]), "r"(a[3]), "r"(b0), "r"(b1));
}

__device__ __forceinline__ uint32_t f2h2(float x, float y) {
    __half2 h = __floats2half2_rn(x, y);
    return *(uint32_t*)&h;
}

// ---------------------------------------------------------------------------
// fp32 -> fp16 conversion pre-pass
// ---------------------------------------------------------------------------
__global__ void cvt_f16_kernel(const float* __restrict__ in,
                               __half* __restrict__ out, int n4) {
    int i = blockIdx.x * blockDim.x + threadIdx.x;
    if (i < n4) {
        float4 v = ((const float4*)in)[i];
        ((__half2*)out)[i * 2 + 0] = __floats2half2_rn(v.x, v.y);
        ((__half2*)out)[i * 2 + 1] = __floats2half2_rn(v.z, v.w);
    }
}

// ---------------------------------------------------------------------------
// FP16 GEMM: C[M,N] = A[M,K]*B[N,K]^T, fp32 accum. Block 128x128x32,
// 256 threads / 8 warps (64x32 warp tiles). 3-stage cp.async, one barrier/iter.
// Smem rows padded to 40 halves (80 B, ldmatrix conflict-free).
// MODE 1: output fp16 to g_qkv, q cols (n0<DM) pre-scaled by 0.125.
// MODE 0: output fp32.
// ---------------------------------------------------------------------------
constexpr int G_STRIDE = 80;                 // bytes per smem row (40 halves)
constexpr int G_STAGE  = 128 * G_STRIDE;     // 10240 B per operand stage
constexpr int GSTG     = 3;
constexpr int GEMM_SMEM = GSTG * 2 * G_STAGE;  // 61440 B

template<int MODE>
__global__ __launch_bounds__(256, 2) void gemm_f16(
    const __half* __restrict__ A, const __half* __restrict__ B,
    void* __restrict__ Cv, int M, int N, int K)
{
    extern __shared__ char sm[];
    char* AsBase = sm;
    char* BsBase = sm + GSTG * G_STAGE;

    const int tid  = threadIdx.x;
    const int lane = tid & 31;
    const int wid  = tid >> 5;
    const int wm   = (wid >> 2) * 64;
    const int wn   = (wid & 3) * 32;
    const int m0   = blockIdx.y * 128;
    const int n0   = blockIdx.x * 128;
    const int NI   = K / 32;

    // ldmatrix per-lane row/byte selectors
    const int grp = lane >> 3, rw = lane & 7;
    const int a_row = (grp & 1) * 8 + rw;   // + wm + mt*16
    const int a_byt = (grp >> 1) * 16;      // + ks*32
    const int b_row = (grp >> 1) * 8 + rw;  // + wn + u*16
    const int b_byt = (grp & 1) * 16;       // + ks*32

    auto issue_tile = [&](int it, int buf) {
        const char* Ag = (const char*)(A + (size_t)m0 * K + it * 32);
        const char* Bg = (const char*)(B + (size_t)n0 * K + it * 32);
        char* As = AsBase + buf * G_STAGE;
        char* Bs = BsBase + buf * G_STAGE;
#pragma unroll
        for (int p = 0; p < 2; ++p) {
            int idx = tid + p * 256;            // 0..511 (128 rows x 4 segs)
            int row = idx >> 2;
            int seg = (idx & 3) * 16;
            cp_async16(As + row * G_STRIDE + seg, Ag + (size_t)row * K * 2 + seg);
            cp_async16(Bs + row * G_STRIDE + seg, Bg + (size_t)row * K * 2 + seg);
        }
        cp_commit();
    };

    float acc[4][4][4];
#pragma unroll
    for (int i = 0; i < 4; ++i)
#pragma unroll
        for (int j = 0; j < 4; ++j)
#pragma unroll
            for (int c = 0; c < 4; ++c) acc[i][j][c] = 0.f;

    issue_tile(0, 0);
    issue_tile(1, 1);

    for (int it = 0; it < NI; ++it) {
        if (it + 1 < NI) cp_wait<1>(); else cp_wait<0>();
        __syncthreads();
        if (it + 2 < NI) issue_tile(it + 2, (it + 2) % GSTG);

        const char* As = AsBase + (it % GSTG) * G_STAGE;
        const char* Bs = BsBase + (it % GSTG) * G_STAGE;
        const uint32_t a_base = smem_u32(As);
        const uint32_t b_base = smem_u32(Bs);

#pragma unroll
        for (int ks = 0; ks < 2; ++ks) {
            uint32_t a[4][4];
#pragma unroll
            for (int mt = 0; mt < 4; ++mt)
                ldmx4(a[mt], a_base + (wm + mt * 16 + a_row) * G_STRIDE
                              + ks * 32 + a_byt);
#pragma unroll
            for (int u = 0; u < 2; ++u) {
                uint32_t b[4];
                ldmx4(b, b_base + (wn + u * 16 + b_row) * G_STRIDE
                          + ks * 32 + b_byt);
#pragma unroll
                for (int mt = 0; mt < 4; ++mt) {
                    mma_f16(acc[mt][2 * u],     a[mt], b[0], b[1]);
                    mma_f16(acc[mt][2 * u + 1], a[mt], b[2], b[3]);
                }
            }
        }
    }

    // Epilogue
#pragma unroll
    for (int mt = 0; mt < 4; ++mt) {
#pragma unroll
        for (int nt = 0; nt < 4; ++nt) {
            int row = m0 + wm + mt * 16 + (lane >> 2);
            int col = n0 + wn + nt * 8 + 2 * (lane & 3);
            if (MODE == 1) {
                __half* C = (__half*)Cv;
                float s = (col < DM) ? 0.125f : 1.0f;
                *(__half2*)&C[(size_t)row * N + col] =
                    __floats2half2_rn(acc[mt][nt][0] * s, acc[mt][nt][1] * s);
                *(__half2*)&C[(size_t)(row + 8) * N + col] =
                    __floats2half2_rn(acc[mt][nt][2] * s, acc[mt][nt][3] * s);
            } else {
                float* C = (float*)Cv;
                *(float2*)&C[(size_t)row * N + col] =
                    make_float2(acc[mt][nt][0], acc[mt][nt][1]);
                *(float2*)&C[(size_t)(row + 8) * N + col] =
                    make_float2(acc[mt][nt][2], acc[mt][nt][3]);
            }
        }
    }
}

// ---------------------------------------------------------------------------
// Flash attention, fp16 mma + ldmatrix. Block = (64-row Q tile, head).
// 128 threads / 4 warps; warp w owns q rows [w*16, w*16+16).
// Q fragments register-resident; P fed back from registers (no smem staging).
// V consumed via ldmatrix.x4.trans. Static smem 45 KB -> 4 blocks/SM.
// ---------------------------------------------------------------------------
constexpr int F_STRIDE = 144;                // bytes per row (72 halves)
constexpr int F_TILE   = 64 * F_STRIDE;      // 9216 B

__global__ __launch_bounds__(128) void flash_f16(
    const __half* __restrict__ qkv, __half* __restrict__ out)
{
    __shared__ char fsm[F_TILE + 2 * F_TILE + 2 * F_TILE];   // Q | K0 K1 | V0 V1
    char* Qs  = fsm;
    char* KsB = fsm + F_TILE;
    char* VsB = fsm + 3 * F_TILE;

    const int tid  = threadIdx.x;
    const int lane = tid & 31;
    const int w    = tid >> 5;
    const int h    = blockIdx.y;
    const int qt   = (int)gridDim.x - 1 - (int)blockIdx.x;  // heavy first
    const int q0   = qt * 64;

    const int grp = lane >> 3, rw = lane & 7;
    const int q_row = (grp & 1) * 8 + rw;    // + w*16
    const int q_byt = (grp >> 1) * 16;       // + ks*32
    const int k_row = (grp >> 1) * 8 + rw;   // + u*16
    const int k_byt = (grp & 1) * 16;        // + ks*32
    const int v_row = (grp & 1) * 8 + rw;    // + ks*16
    const int v_byt = (grp >> 1) * 16;       // + u*32

    const char* qg = (const char*)(qkv + (size_t)q0 * QKV_N + h * HD);

    auto issue_kv = [&](int t, int buf) {
        const char* kg = (const char*)(qkv + (size_t)(t * 64) * QKV_N + DM + h * HD);
        const char* vg = kg + DM * 2;
        char* Ks = KsB + buf * F_TILE;
        char* Vs = VsB + buf * F_TILE;
#pragma unroll
        for (int p = 0; p < 4; ++p) {
            int idx = tid + p * 128;          // 0..511 (64 rows x 8 segs)
            int row = idx >> 3;
            int seg = (idx & 7) * 16;
            cp_async16(Ks + row * F_STRIDE + seg, kg + (size_t)row * QKV_N * 2 + seg);
            cp_async16(Vs + row * F_STRIDE + seg, vg + (size_t)row * QKV_N * 2 + seg);
        }
        cp_commit();
    };

    // Prologue: Q, then KV tile 0
    {
#pragma unroll
        for (int p = 0; p < 4; ++p) {
            int idx = tid + p * 128;
            int row = idx >> 3;
            int seg = (idx & 7) * 16;
            cp_async16(Qs + row * F_STRIDE + seg, qg + (size_t)row * QKV_N * 2 + seg);
        }
        cp_commit();
    }
    issue_kv(0, 0);

    const int r  = (lane >> 2);
    const int qr = w * 16 + r;                // local q row (and qr+8)
    uint32_t Qf[4][4];                        // Q fragments, loaded at t=0
    float m_i[2] = {-1e30f, -1e30f};
    float l_i[2] = {0.f, 0.f};
    float oacc[8][4];
#pragma unroll
    for (int n = 0; n < 8; ++n)
#pragma unroll
        for (int c = 0; c < 4; ++c) oacc[n][c] = 0.f;

    const uint32_t q_base = smem_u32(Qs);

    for (int t = 0; t <= qt; ++t) {
        cp_wait<0>();
        __syncthreads();
        if (t + 1 <= qt) issue_kv(t + 1, (t + 1) & 1);

        if (t == 0) {
#pragma unroll
            for (int ks = 0; ks < 4; ++ks)
                ldmx4(Qf[ks], q_base + (w * 16 + q_row) * F_STRIDE + ks * 32 + q_byt);
        }

        const uint32_t k_base = smem_u32(KsB + (t & 1) * F_TILE);
        const uint32_t v_base = smem_u32(VsB + (t & 1) * F_TILE);

        // S = Q K^T  (q pre-scaled by 0.125 upstream)
        float sacc[8][4];
#pragma unroll
        for (int n = 0; n < 8; ++n)
#pragma unroll
            for (int c = 0; c < 4; ++c) sacc[n][c] = 0.f;

#pragma unroll
        for (int ks = 0; ks < 4; ++ks) {
#pragma unroll
            for (int u = 0; u < 4; ++u) {
                uint32_t b[4];
                ldmx4(b, k_base + (u * 16 + k_row) * F_STRIDE + ks * 32 + k_byt);
                mma_f16(sacc[2 * u],     Qf[ks], b[0], b[1]);
                mma_f16(sacc[2 * u + 1], Qf[ks], b[2], b[3]);
            }
        }

        // Causal mask on the diagonal tile
        if (t == qt) {
#pragma unroll
            for (int nt = 0; nt < 8; ++nt) {
#pragma unroll
                for (int c = 0; c < 4; ++c) {
                    int col = nt * 8 + 2 * (lane & 3) + (c & 1);
                    int rowL = qr + (c >> 1) * 8;
                    if (col > rowL) sacc[nt][c] = -1e30f;
                }
            }
        }

        // Online softmax
        float alpha[2];
#pragma unroll
        for (int half = 0; half < 2; ++half) {
            float mx = -1e30f;
#pragma unroll
            for (int nt = 0; nt < 8; ++nt) {
                mx = fmaxf(mx, sacc[nt][half * 2]);
                mx = fmaxf(mx, sacc[nt][half * 2 + 1]);
            }
            mx = fmaxf(mx, __shfl_xor_sync(0xffffffffu, mx, 1, 4));
            mx = fmaxf(mx, __shfl_xor_sync(0xffffffffu, mx, 2, 4));
            float mnew = fmaxf(m_i[half], mx);
            alpha[half] = __expf(m_i[half] - mnew);
            m_i[half] = mnew;
            float rs = 0.f;
#pragma unroll
            for (int nt = 0; nt < 8; ++nt) {
                float p0 = __expf(sacc[nt][half * 2]     - mnew);
                float p1 = __expf(sacc[nt][half * 2 + 1] - mnew);
                sacc[nt][half * 2]     = p0;
                sacc[nt][half * 2 + 1] = p1;
                rs += p0 + p1;
            }
            rs += __shfl_xor_sync(0xffffffffu, rs, 1, 4);
            rs += __shfl_xor_sync(0xffffffffu, rs, 2, 4);
            l_i[half] = l_i[half] * alpha[half] + rs;
        }

#pragma unroll
        for (int nt = 0; nt < 8; ++nt) {
            oacc[nt][0] *= alpha[0]; oacc[nt][1] *= alpha[0];
            oacc[nt][2] *= alpha[1]; oacc[nt][3] *= alpha[1];
        }

        // P fragments directly from registers (S-frag layout == A-frag layout)
        uint32_t pa[4][4];
#pragma unroll
        for (int ks = 0; ks < 4; ++ks) {
            pa[ks][0] = f2h2(sacc[2 * ks][0],     sacc[2 * ks][1]);
            pa[ks][1] = f2h2(sacc[2 * ks][2],     sacc[2 * ks][3]);
            pa[ks][2] = f2h2(sacc[2 * ks + 1][0], sacc[2 * ks + 1][1]);
            pa[ks][3] = f2h2(sacc[2 * ks + 1][2], sacc[2 * ks + 1][3]);
        }

        // O += P V  (V via ldmatrix.trans)
#pragma unroll
        for (int ks = 0; ks < 4; ++ks) {
#pragma unroll
            for (int u = 0; u < 4; ++u) {
                uint32_t b[4];
                ldmx4t(b, v_base + (ks * 16 + v_row) * F_STRIDE + u * 32 + v_byt);
                mma_f16(oacc[2 * u],     pa[ks], b[0], b[1]);
                mma_f16(oacc[2 * u + 1], pa[ks], b[2], b[3]);
            }
        }
    }

    // Epilogue: normalize, convert fp16, store
    float inv0 = 1.f / l_i[0];
    float inv1 = 1.f / l_i[1];
#pragma unroll
    for (int nt = 0; nt < 8; ++nt) {
        int col = h * HD + nt * 8 + 2 * (lane & 3);
        int row = q0 + qr;
        *(__half2*)&out[(size_t)row * DM + col] =
            __floats2half2_rn(oacc[nt][0] * inv0, oacc[nt][1] * inv0);
        *(__half2*)&out[(size_t)(row + 8) * DM + col] =
            __floats2half2_rn(oacc[nt][2] * inv1, oacc[nt][3] * inv1);
    }
}

// ---------------------------------------------------------------------------
// Launch
// ---------------------------------------------------------------------------
extern "C" void kernel_launch(void* const* d_in, const int* in_sizes, int n_in,
                              void* d_out, int out_size)
{
    const float* x     = (const float*)d_in[0];
    const float* w_qkv = (const float*)d_in[1];
    const float* w_out = (const float*)d_in[2];
    float* out = (float*)d_out;

    __half *xr, *wqkvr, *woutr, *qkvp, *attp;
    cudaGetSymbolAddress((void**)&xr,    g_x);
    cudaGetSymbolAddress((void**)&wqkvr, g_wqkv);
    cudaGetSymbolAddress((void**)&woutr, g_wout);
    cudaGetSymbolAddress((void**)&qkvp,  g_qkv);
    cudaGetSymbolAddress((void**)&attp,  g_att);

    cudaFuncSetAttribute(gemm_f16<1>,
                         cudaFuncAttributeMaxDynamicSharedMemorySize, GEMM_SMEM);
    cudaFuncSetAttribute(gemm_f16<0>,
                         cudaFuncAttributeMaxDynamicSharedMemorySize, GEMM_SMEM);

    // 0) fp32 -> fp16 inputs
    {
        int n4;
        n4 = S_LEN * DM / 4;
        cvt_f16_kernel<<<(n4 + 255) / 256, 256>>>(x, xr, n4);
        n4 = QKV_N * DM / 4;
        cvt_f16_kernel<<<(n4 + 255) / 256, 256>>>(w_qkv, wqkvr, n4);
        n4 = DM * DM / 4;
        cvt_f16_kernel<<<(n4 + 255) / 256, 256>>>(w_out, woutr, n4);
    }
    // 1) QKV projection (fp16 out, q pre-scaled by 0.125)
    {
        dim3 grid(QKV_N / 128, S_LEN / 128);
        gemm_f16<1><<<grid, 256, GEMM_SMEM>>>(xr, wqkvr, qkvp, S_LEN, QKV_N, DM);
    }
    // 2) Flash attention (fp16 out)
    {
        dim3 grid(S_LEN / 64, NH);
        flash_f16<<<grid, 128>>>(qkvp, attp);
    }
    // 3) Output projection (fp32 out)
    {
        dim3 grid(DM / 128, S_LEN / 128);
        gemm_f16<0><<<grid, 256, GEMM_SMEM>>>(attp, woutr, out, S_LEN, DM, DM);
    }
}

// round 9
// speedup vs baseline: 2.5249x; 1.0395x over previous
#include <cuda_runtime.h>
#include <cuda_fp16.h>
#include <cstdint>

// Problem constants
constexpr int S_LEN = 4096;
constexpr int DM    = 1024;
constexpr int NH    = 16;
constexpr int HD    = 64;
constexpr int QKV_N = 3 * DM;  // 3072

// q section scaled by 0.125*log2(e): softmax computed in exp2 domain.
constexpr float Q_SCALE = 0.125f * 1.4426950408889634f;

// Scratch device globals — fp16
__device__ __half g_x   [(size_t)S_LEN * DM];
__device__ __half g_wqkv[(size_t)QKV_N * DM];
__device__ __half g_wout[(size_t)DM * DM];
__device__ __half g_qkv [(size_t)S_LEN * QKV_N];
__device__ __half g_att [(size_t)S_LEN * DM];

// ---------------------------------------------------------------------------
// Helpers
// ---------------------------------------------------------------------------
__device__ __forceinline__ void cp_async16(void* smem_dst, const void* gmem_src) {
    uint32_t s = (uint32_t)__cvta_generic_to_shared(smem_dst);
    asm volatile("cp.async.cg.shared.global [%0], [%1], 16;" :: "r"(s), "l"(gmem_src));
}
__device__ __forceinline__ void cp_commit() {
    asm volatile("cp.async.commit_group;");
}
template<int N>
__device__ __forceinline__ void cp_wait() {
    asm volatile("cp.async.wait_group %0;" :: "n"(N));
}
__device__ __forceinline__ uint32_t smem_u32(const void* p) {
    return (uint32_t)__cvta_generic_to_shared(p);
}
__device__ __forceinline__ float ex2(float x) {
    float y;
    asm("ex2.approx.ftz.f32 %0, %1;" : "=f"(y) : "f"(x));
    return y;
}
__device__ __forceinline__ void ldmx4(uint32_t r[4], uint32_t a) {
    asm volatile("ldmatrix.sync.aligned.m8n8.x4.shared.b16 {%0,%1,%2,%3}, [%4];"
                 : "=r"(r[0]), "=r"(r[1]), "=r"(r[2]), "=r"(r[3]) : "r"(a));
}
__device__ __forceinline__ void ldmx4t(uint32_t r[4], uint32_t a) {
    asm volatile("ldmatrix.sync.aligned.m8n8.x4.trans.shared.b16 {%0,%1,%2,%3}, [%4];"
                 : "=r"(r[0]), "=r"(r[1]), "=r"(r[2]), "=r"(r[3]) : "r"(a));
}
__device__ __forceinline__ void mma_f16(float c[4], const uint32_t a[4],
                                        uint32_t b0, uint32_t b1) {
    asm volatile(
        "mma.sync.aligned.m16n8k16.row.col.f32.f16.f16.f32 "
        "{%0,%1,%2,%3}, {%4,%5,%6,%7}, {%8,%9}, {%0,%1,%2,%3};"
        : "+f"(c[0]), "+f"(c[1]), "+f"(c[2]), "+f"(c[3])
        : "r"(a[0]), "r"(a[1]), "r"(a[2]), "r"(a[3]), "r"(b0), "r"(b1));
}
__device__ __forceinline__ uint32_t f2h2(float x, float y) {
    __half2 h = __floats2half2_rn(x, y);
    return *(uint32_t*)&h;
}

// ---------------------------------------------------------------------------
// fp32 -> fp16 conversion pre-pass
// ---------------------------------------------------------------------------
__global__ void cvt_f16_kernel(const float* __restrict__ in,
                               __half* __restrict__ out, int n4) {
    int i = blockIdx.x * blockDim.x + threadIdx.x;
    if (i < n4) {
        float4 v = ((const float4*)in)[i];
        ((__half2*)out)[i * 2 + 0] = __floats2half2_rn(v.x, v.y);
        ((__half2*)out)[i * 2 + 1] = __floats2half2_rn(v.z, v.w);
    }
}

// ---------------------------------------------------------------------------
// FP16 GEMM: C[M,N] = A[M,K]*B[N,K]^T, fp32 accum. Block 128x128x32,
// 128 threads / 4 warps, 64x64 warp tiles (8 ldmatrix feed 32 mma per k16).
// 3-stage cp.async, one barrier per K-iter.
// MODE 1: fp16 out; q cols (col<DM) scaled by Q_SCALE.  MODE 0: fp32 out.
// ---------------------------------------------------------------------------
constexpr int G_STRIDE = 80;                  // bytes per smem row (40 halves)
constexpr int G_STAGE  = 128 * G_STRIDE;      // 10240 B per operand stage
constexpr int GSTG     = 3;
constexpr int GEMM_SMEM = GSTG * 2 * G_STAGE; // 61440 B

template<int MODE>
__global__ __launch_bounds__(128) void gemm_f16(
    const __half* __restrict__ A, const __half* __restrict__ B,
    void* __restrict__ Cv, int M, int N, int K)
{
    extern __shared__ char sm[];
    char* AsBase = sm;
    char* BsBase = sm + GSTG * G_STAGE;

    const int tid  = threadIdx.x;
    const int lane = tid & 31;
    const int wid  = tid >> 5;
    const int wm   = (wid >> 1) * 64;
    const int wn   = (wid & 1) * 64;
    const int m0   = blockIdx.y * 128;
    const int n0   = blockIdx.x * 128;
    const int NI   = K / 32;

    const int grp = lane >> 3, rw = lane & 7;
    const int a_row = (grp & 1) * 8 + rw;
    const int a_byt = (grp >> 1) * 16;
    const int b_row = (grp >> 1) * 8 + rw;
    const int b_byt = (grp & 1) * 16;

    auto issue_tile = [&](int it, int buf) {
        const char* Ag = (const char*)(A + (size_t)m0 * K + it * 32);
        const char* Bg = (const char*)(B + (size_t)n0 * K + it * 32);
        char* As = AsBase + buf * G_STAGE;
        char* Bs = BsBase + buf * G_STAGE;
#pragma unroll
        for (int p = 0; p < 4; ++p) {
            int idx = tid + p * 128;            // 0..511 (128 rows x 4 segs)
            int row = idx >> 2;
            int seg = (idx & 3) * 16;
            cp_async16(As + row * G_STRIDE + seg, Ag + (size_t)row * K * 2 + seg);
            cp_async16(Bs + row * G_STRIDE + seg, Bg + (size_t)row * K * 2 + seg);
        }
        cp_commit();
    };

    float acc[4][8][4];
#pragma unroll
    for (int i = 0; i < 4; ++i)
#pragma unroll
        for (int j = 0; j < 8; ++j)
#pragma unroll
            for (int c = 0; c < 4; ++c) acc[i][j][c] = 0.f;

    issue_tile(0, 0);
    issue_tile(1, 1);

    for (int it = 0; it < NI; ++it) {
        if (it + 1 < NI) cp_wait<1>(); else cp_wait<0>();
        __syncthreads();
        if (it + 2 < NI) issue_tile(it + 2, (it + 2) % GSTG);

        const uint32_t a_base = smem_u32(AsBase + (it % GSTG) * G_STAGE);
        const uint32_t b_base = smem_u32(BsBase + (it % GSTG) * G_STAGE);

#pragma unroll
        for (int ks = 0; ks < 2; ++ks) {
            uint32_t a[4][4], b[4][4];
#pragma unroll
            for (int mt = 0; mt < 4; ++mt)
                ldmx4(a[mt], a_base + (wm + mt * 16 + a_row) * G_STRIDE
                              + ks * 32 + a_byt);
#pragma unroll
            for (int u = 0; u < 4; ++u)
                ldmx4(b[u], b_base + (wn + u * 16 + b_row) * G_STRIDE
                             + ks * 32 + b_byt);
#pragma unroll
            for (int mt = 0; mt < 4; ++mt)
#pragma unroll
                for (int u = 0; u < 4; ++u) {
                    mma_f16(acc[mt][2 * u],     a[mt], b[u][0], b[u][1]);
                    mma_f16(acc[mt][2 * u + 1], a[mt], b[u][2], b[u][3]);
                }
        }
    }

    // Epilogue
#pragma unroll
    for (int mt = 0; mt < 4; ++mt) {
#pragma unroll
        for (int nt = 0; nt < 8; ++nt) {
            int row = m0 + wm + mt * 16 + (lane >> 2);
            int col = n0 + wn + nt * 8 + 2 * (lane & 3);
            if (MODE == 1) {
                __half* C = (__half*)Cv;
                float s = (col < DM) ? Q_SCALE : 1.0f;
                *(__half2*)&C[(size_t)row * N + col] =
                    __floats2half2_rn(acc[mt][nt][0] * s, acc[mt][nt][1] * s);
                *(__half2*)&C[(size_t)(row + 8) * N + col] =
                    __floats2half2_rn(acc[mt][nt][2] * s, acc[mt][nt][3] * s);
            } else {
                float* C = (float*)Cv;
                *(float2*)&C[(size_t)row * N + col] =
                    make_float2(acc[mt][nt][0], acc[mt][nt][1]);
                *(float2*)&C[(size_t)(row + 8) * N + col] =
                    make_float2(acc[mt][nt][2], acc[mt][nt][3]);
            }
        }
    }
}

// ---------------------------------------------------------------------------
// Flash attention, fp16 mma + ldmatrix, 128-col KV pairs per softmax.
// Block = (64-row Q tile, head), 128 threads / 4 warps.
// KV pair buffers (2x 128 rows), 2-deep pipeline, one barrier per pair.
// Softmax in exp2 domain (q pre-scaled by 0.125*log2e upstream).
// Smem 82944 B dynamic -> 2 blocks/SM.
// ---------------------------------------------------------------------------
constexpr int F_STRIDE = 144;                 // bytes per row (72 halves)
constexpr int F_TILE   = 64 * F_STRIDE;       // 9216 B
constexpr int F_PAIR   = 2 * F_TILE;          // 18432 B (128-row pair buffer)
constexpr int FL_SMEM  = F_TILE + 4 * F_PAIR; // Q | K0 K1 | V0 V1 = 82944 B

__global__ __launch_bounds__(128) void flash_f16(
    const __half* __restrict__ qkv, __half* __restrict__ out)
{
    extern __shared__ char fsm[];
    char* Qs  = fsm;
    char* KsB = fsm + F_TILE;
    char* VsB = fsm + F_TILE + 2 * F_PAIR;

    const int tid  = threadIdx.x;
    const int lane = tid & 31;
    const int w    = tid >> 5;
    const int h    = blockIdx.y;
    const int qt   = (int)gridDim.x - 1 - (int)blockIdx.x;  // heavy first
    const int q0   = qt * 64;
    const int pmax = qt >> 1;                 // KV pairs 0..pmax (128 cols each)

    const int grp = lane >> 3, rw = lane & 7;
    const int q_row = (grp & 1) * 8 + rw;
    const int q_byt = (grp >> 1) * 16;
    const int k_row = (grp >> 1) * 8 + rw;
    const int k_byt = (grp & 1) * 16;
    const int v_row = (grp & 1) * 8 + rw;
    const int v_byt = (grp >> 1) * 16;

    const char* qg = (const char*)(qkv + (size_t)q0 * QKV_N + h * HD);

    auto issue_pair = [&](int p, int buf) {
        char* Ks = KsB + buf * F_PAIR;
        char* Vs = VsB + buf * F_PAIR;
#pragma unroll
        for (int half = 0; half < 2; ++half) {
            int tile = 2 * p + half;
            if (tile > S_LEN / 64 - 1) tile = S_LEN / 64 - 1;  // clamp; masked anyway
            const char* kg = (const char*)(qkv + (size_t)(tile * 64) * QKV_N + DM + h * HD);
            const char* vg = kg + DM * 2;
#pragma unroll
            for (int pp = 0; pp < 4; ++pp) {
                int idx = tid + pp * 128;     // 0..511 (64 rows x 8 segs)
                int row = idx >> 3;
                int seg = (idx & 7) * 16;
                cp_async16(Ks + (half * 64 + row) * F_STRIDE + seg,
                           kg + (size_t)row * QKV_N * 2 + seg);
                cp_async16(Vs + (half * 64 + row) * F_STRIDE + seg,
                           vg + (size_t)row * QKV_N * 2 + seg);
            }
        }
        cp_commit();
    };

    // Prologue: Q then pair 0
    {
#pragma unroll
        for (int pp = 0; pp < 4; ++pp) {
            int idx = tid + pp * 128;
            int row = idx >> 3;
            int seg = (idx & 7) * 16;
            cp_async16(Qs + row * F_STRIDE + seg, qg + (size_t)row * QKV_N * 2 + seg);
        }
        cp_commit();
    }
    issue_pair(0, 0);

    const int r  = (lane >> 2);
    const int qr = w * 16 + r;
    uint32_t Qf[4][4];
    float m_i[2] = {-1e30f, -1e30f};
    float l_i[2] = {0.f, 0.f};
    float oacc[8][4];
#pragma unroll
    for (int n = 0; n < 8; ++n)
#pragma unroll
        for (int c = 0; c < 4; ++c) oacc[n][c] = 0.f;

    const uint32_t q_base = smem_u32(Qs);

    for (int p = 0; p <= pmax; ++p) {
        cp_wait<0>();
        __syncthreads();
        if (p + 1 <= pmax) issue_pair(p + 1, (p + 1) & 1);

        if (p == 0) {
#pragma unroll
            for (int ks = 0; ks < 4; ++ks)
                ldmx4(Qf[ks], q_base + (w * 16 + q_row) * F_STRIDE + ks * 32 + q_byt);
        }

        const uint32_t k_base = smem_u32(KsB + (p & 1) * F_PAIR);
        const uint32_t v_base = smem_u32(VsB + (p & 1) * F_PAIR);

        // S = Q K^T over 128 cols
        float sacc[16][4];
#pragma unroll
        for (int n = 0; n < 16; ++n)
#pragma unroll
            for (int c = 0; c < 4; ++c) sacc[n][c] = 0.f;

#pragma unroll
        for (int ks = 0; ks < 4; ++ks) {
#pragma unroll
            for (int u = 0; u < 8; ++u) {
                uint32_t b[4];
                ldmx4(b, k_base + (u * 16 + k_row) * F_STRIDE + ks * 32 + k_byt);
                mma_f16(sacc[2 * u],     Qf[ks], b[0], b[1]);
                mma_f16(sacc[2 * u + 1], Qf[ks], b[2], b[3]);
            }
        }

        // Causal mask — only the last pair straddles/exceeds the diagonal
        if (p == pmax) {
#pragma unroll
            for (int nt = 0; nt < 16; ++nt) {
#pragma unroll
                for (int c = 0; c < 4; ++c) {
                    int col_g = p * 128 + nt * 8 + 2 * (lane & 3) + (c & 1);
                    int row_g = q0 + qr + (c >> 1) * 8;
                    if (col_g > row_g) sacc[nt][c] = -1e30f;
                }
            }
        }

        // Online softmax (exp2 domain) over 128 cols
        float alpha[2];
#pragma unroll
        for (int half = 0; half < 2; ++half) {
            float mx = -1e30f;
#pragma unroll
            for (int nt = 0; nt < 16; ++nt) {
                mx = fmaxf(mx, sacc[nt][half * 2]);
                mx = fmaxf(mx, sacc[nt][half * 2 + 1]);
            }
            mx = fmaxf(mx, __shfl_xor_sync(0xffffffffu, mx, 1, 4));
            mx = fmaxf(mx, __shfl_xor_sync(0xffffffffu, mx, 2, 4));
            float mnew = fmaxf(m_i[half], mx);
            alpha[half] = ex2(m_i[half] - mnew);
            m_i[half] = mnew;
            float rs = 0.f;
#pragma unroll
            for (int nt = 0; nt < 16; ++nt) {
                float p0 = ex2(sacc[nt][half * 2]     - mnew);
                float p1 = ex2(sacc[nt][half * 2 + 1] - mnew);
                sacc[nt][half * 2]     = p0;
                sacc[nt][half * 2 + 1] = p1;
                rs += p0 + p1;
            }
            rs += __shfl_xor_sync(0xffffffffu, rs, 1, 4);
            rs += __shfl_xor_sync(0xffffffffu, rs, 2, 4);
            l_i[half] = l_i[half] * alpha[half] + rs;
        }

#pragma unroll
        for (int nt = 0; nt < 8; ++nt) {
            oacc[nt][0] *= alpha[0]; oacc[nt][1] *= alpha[0];
            oacc[nt][2] *= alpha[1]; oacc[nt][3] *= alpha[1];
        }

        // Pack P fragments from registers (S-frag layout == A-frag layout)
        uint32_t pa[8][4];
#pragma unroll
        for (int ks = 0; ks < 8; ++ks) {
            pa[ks][0] = f2h2(sacc[2 * ks][0],     sacc[2 * ks][1]);
            pa[ks][1] = f2h2(sacc[2 * ks][2],     sacc[2 * ks][3]);
            pa[ks][2] = f2h2(sacc[2 * ks + 1][0], sacc[2 * ks + 1][1]);
            pa[ks][3] = f2h2(sacc[2 * ks + 1][2], sacc[2 * ks + 1][3]);
        }

        // O += P V  (V via ldmatrix.trans; k = 128 rows of the pair)
#pragma unroll
        for (int ks = 0; ks < 8; ++ks) {
#pragma unroll
            for (int u = 0; u < 4; ++u) {
                uint32_t b[4];
                ldmx4t(b, v_base + (ks * 16 + v_row) * F_STRIDE + u * 32 + v_byt);
                mma_f16(oacc[2 * u],     pa[ks], b[0], b[1]);
                mma_f16(oacc[2 * u + 1], pa[ks], b[2], b[3]);
            }
        }
    }

    // Epilogue
    float inv0 = 1.f / l_i[0];
    float inv1 = 1.f / l_i[1];
#pragma unroll
    for (int nt = 0; nt < 8; ++nt) {
        int col = h * HD + nt * 8 + 2 * (lane & 3);
        int row = q0 + qr;
        *(__half2*)&out[(size_t)row * DM + col] =
            __floats2half2_rn(oacc[nt][0] * inv0, oacc[nt][1] * inv0);
        *(__half2*)&out[(size_t)(row + 8) * DM + col] =
            __floats2half2_rn(oacc[nt][2] * inv1, oacc[nt][3] * inv1);
    }
}

// ---------------------------------------------------------------------------
// Launch
// ---------------------------------------------------------------------------
extern "C" void kernel_launch(void* const* d_in, const int* in_sizes, int n_in,
                              void* d_out, int out_size)
{
    const float* x     = (const float*)d_in[0];
    const float* w_qkv = (const float*)d_in[1];
    const float* w_out = (const float*)d_in[2];
    float* out = (float*)d_out;

    __half *xr, *wqkvr, *woutr, *qkvp, *attp;
    cudaGetSymbolAddress((void**)&xr,    g_x);
    cudaGetSymbolAddress((void**)&wqkvr, g_wqkv);
    cudaGetSymbolAddress((void**)&woutr, g_wout);
    cudaGetSymbolAddress((void**)&qkvp,  g_qkv);
    cudaGetSymbolAddress((void**)&attp,  g_att);

    cudaFuncSetAttribute(gemm_f16<1>,
                         cudaFuncAttributeMaxDynamicSharedMemorySize, GEMM_SMEM);
    cudaFuncSetAttribute(gemm_f16<0>,
                         cudaFuncAttributeMaxDynamicSharedMemorySize, GEMM_SMEM);
    cudaFuncSetAttribute(flash_f16,
                         cudaFuncAttributeMaxDynamicSharedMemorySize, FL_SMEM);

    // 0) fp32 -> fp16 inputs
    {
        int n4;
        n4 = S_LEN * DM / 4;
        cvt_f16_kernel<<<(n4 + 255) / 256, 256>>>(x, xr, n4);
        n4 = QKV_N * DM / 4;
        cvt_f16_kernel<<<(n4 + 255) / 256, 256>>>(w_qkv, wqkvr, n4);
        n4 = DM * DM / 4;
        cvt_f16_kernel<<<(n4 + 255) / 256, 256>>>(w_out, woutr, n4);
    }
    // 1) QKV projection (fp16 out; q scaled by 0.125*log2e)
    {
        dim3 grid(QKV_N / 128, S_LEN / 128);
        gemm_f16<1><<<grid, 128, GEMM_SMEM>>>(xr, wqkvr, qkvp, S_LEN, QKV_N, DM);
    }
    // 2) Flash attention (fp16 out)
    {
        dim3 grid(S_LEN / 64, NH);
        flash_f16<<<grid, 128, FL_SMEM>>>(qkvp, attp);
    }
    // 3) Output projection (fp32 out)
    {
        dim3 grid(DM / 128, S_LEN / 128);
        gemm_f16<0><<<grid, 128, GEMM_SMEM>>>(attp, woutr, out, S_LEN, DM, DM);
    }
}

// round 11
// speedup vs baseline: 2.5720x; 1.0187x over previous
#include <cuda_runtime.h>
#include <cuda_fp16.h>
#include <cstdint>

// Problem constants
constexpr int S_LEN = 4096;
constexpr int DM    = 1024;
constexpr int NH    = 16;
constexpr int HD    = 64;
constexpr int QKV_N = 3 * DM;  // 3072

// q section scaled by 0.125*log2(e): softmax computed in exp2 domain.
constexpr float Q_SCALE = 0.125f * 1.4426950408889634f;

// Scratch device globals — fp16
__device__ __half g_x   [(size_t)S_LEN * DM];
__device__ __half g_wqkv[(size_t)QKV_N * DM];
__device__ __half g_wout[(size_t)DM * DM];
__device__ __half g_qkv [(size_t)S_LEN * QKV_N];
__device__ __half g_att [(size_t)S_LEN * DM];

// ---------------------------------------------------------------------------
// Helpers
// ---------------------------------------------------------------------------
__device__ __forceinline__ void cp_async16(void* smem_dst, const void* gmem_src) {
    uint32_t s = (uint32_t)__cvta_generic_to_shared(smem_dst);
    asm volatile("cp.async.cg.shared.global [%0], [%1], 16;" :: "r"(s), "l"(gmem_src));
}
__device__ __forceinline__ void cp_commit() {
    asm volatile("cp.async.commit_group;");
}
template<int N>
__device__ __forceinline__ void cp_wait() {
    asm volatile("cp.async.wait_group %0;" :: "n"(N));
}
__device__ __forceinline__ uint32_t smem_u32(const void* p) {
    return (uint32_t)__cvta_generic_to_shared(p);
}
__device__ __forceinline__ float ex2(float x) {
    float y;
    asm("ex2.approx.ftz.f32 %0, %1;" : "=f"(y) : "f"(x));
    return y;
}
// packed half2 exp2 — one MUFU op for two values
__device__ __forceinline__ uint32_t h2ex2(uint32_t x) {
    uint32_t y;
    asm("ex2.approx.f16x2 %0, %1;" : "=r"(y) : "r"(x));
    return y;
}
__device__ __forceinline__ void ldmx4(uint32_t r[4], uint32_t a) {
    asm volatile("ldmatrix.sync.aligned.m8n8.x4.shared.b16 {%0,%1,%2,%3}, [%4];"
                 : "=r"(r[0]), "=r"(r[1]), "=r"(r[2]), "=r"(r[3]) : "r"(a));
}
__device__ __forceinline__ void ldmx4t(uint32_t r[4], uint32_t a) {
    asm volatile("ldmatrix.sync.aligned.m8n8.x4.trans.shared.b16 {%0,%1,%2,%3}, [%4];"
                 : "=r"(r[0]), "=r"(r[1]), "=r"(r[2]), "=r"(r[3]) : "r"(a));
}
__device__ __forceinline__ void mma_f16(float c[4], const uint32_t a[4],
                                        uint32_t b0, uint32_t b1) {
    asm volatile(
        "mma.sync.aligned.m16n8k16.row.col.f32.f16.f16.f32 "
        "{%0,%1,%2,%3}, {%4,%5,%6,%7}, {%8,%9}, {%0,%1,%2,%3};"
        : "+f"(c[0]), "+f"(c[1]), "+f"(c[2]), "+f"(c[3])
        : "r"(a[0]), "r"(a[1]), "r"(a[2]), "r"(a[3]), "r"(b0), "r"(b1));
}
__device__ __forceinline__ uint32_t f2h2(float x, float y) {
    __half2 h = __floats2half2_rn(x, y);
    return *(uint32_t*)&h;
}

// ---------------------------------------------------------------------------
// fp32 -> fp16 conversion pre-pass: all three tensors, ONE launch
// ---------------------------------------------------------------------------
__global__ void cvt_all_kernel(const float* __restrict__ a, __half* __restrict__ oa, int na4,
                               const float* __restrict__ b, __half* __restrict__ ob, int nb4,
                               const float* __restrict__ c, __half* __restrict__ oc, int nc4) {
    int j = blockIdx.x * blockDim.x + threadIdx.x;
    const float* in; __half* out;
    if (j < na4) { in = a; out = oa; }
    else {
        j -= na4;
        if (j < nb4) { in = b; out = ob; }
        else {
            j -= nb4;
            if (j >= nc4) return;
            in = c; out = oc;
        }
    }
    float4 v = ((const float4*)in)[j];
    ((__half2*)out)[j * 2 + 0] = __floats2half2_rn(v.x, v.y);
    ((__half2*)out)[j * 2 + 1] = __floats2half2_rn(v.z, v.w);
}

// ---------------------------------------------------------------------------
// FP16 GEMM: C[M,N] = A[M,K]*B[N,K]^T, fp32 accum. Block 128x128x32,
// 128 threads / 4 warps, 64x64 warp tiles. 3-stage cp.async, 1 barrier/iter.
// MODE 1: fp16 out; q cols (col<DM) scaled by Q_SCALE.  MODE 0: fp32 out.
// ---------------------------------------------------------------------------
constexpr int G_STRIDE = 80;
constexpr int G_STAGE  = 128 * G_STRIDE;
constexpr int GSTG     = 3;
constexpr int GEMM_SMEM = GSTG * 2 * G_STAGE;  // 61440 B

template<int MODE>
__global__ __launch_bounds__(128) void gemm_f16(
    const __half* __restrict__ A, const __half* __restrict__ B,
    void* __restrict__ Cv, int M, int N, int K)
{
    extern __shared__ char sm[];
    char* AsBase = sm;
    char* BsBase = sm + GSTG * G_STAGE;

    const int tid  = threadIdx.x;
    const int lane = tid & 31;
    const int wid  = tid >> 5;
    const int wm   = (wid >> 1) * 64;
    const int wn   = (wid & 1) * 64;
    const int m0   = blockIdx.y * 128;
    const int n0   = blockIdx.x * 128;
    const int NI   = K / 32;

    const int grp = lane >> 3, rw = lane & 7;
    const int a_row = (grp & 1) * 8 + rw;
    const int a_byt = (grp >> 1) * 16;
    const int b_row = (grp >> 1) * 8 + rw;
    const int b_byt = (grp & 1) * 16;

    auto issue_tile = [&](int it, int buf) {
        const char* Ag = (const char*)(A + (size_t)m0 * K + it * 32);
        const char* Bg = (const char*)(B + (size_t)n0 * K + it * 32);
        char* As = AsBase + buf * G_STAGE;
        char* Bs = BsBase + buf * G_STAGE;
#pragma unroll
        for (int p = 0; p < 4; ++p) {
            int idx = tid + p * 128;
            int row = idx >> 2;
            int seg = (idx & 3) * 16;
            cp_async16(As + row * G_STRIDE + seg, Ag + (size_t)row * K * 2 + seg);
            cp_async16(Bs + row * G_STRIDE + seg, Bg + (size_t)row * K * 2 + seg);
        }
        cp_commit();
    };

    float acc[4][8][4];
#pragma unroll
    for (int i = 0; i < 4; ++i)
#pragma unroll
        for (int j = 0; j < 8; ++j)
#pragma unroll
            for (int c = 0; c < 4; ++c) acc[i][j][c] = 0.f;

    issue_tile(0, 0);
    issue_tile(1, 1);

    for (int it = 0; it < NI; ++it) {
        if (it + 1 < NI) cp_wait<1>(); else cp_wait<0>();
        __syncthreads();
        if (it + 2 < NI) issue_tile(it + 2, (it + 2) % GSTG);

        const uint32_t a_base = smem_u32(AsBase + (it % GSTG) * G_STAGE);
        const uint32_t b_base = smem_u32(BsBase + (it % GSTG) * G_STAGE);

#pragma unroll
        for (int ks = 0; ks < 2; ++ks) {
            uint32_t a[4][4], b[4][4];
#pragma unroll
            for (int mt = 0; mt < 4; ++mt)
                ldmx4(a[mt], a_base + (wm + mt * 16 + a_row) * G_STRIDE
                              + ks * 32 + a_byt);
#pragma unroll
            for (int u = 0; u < 4; ++u)
                ldmx4(b[u], b_base + (wn + u * 16 + b_row) * G_STRIDE
                             + ks * 32 + b_byt);
#pragma unroll
            for (int mt = 0; mt < 4; ++mt)
#pragma unroll
                for (int u = 0; u < 4; ++u) {
                    mma_f16(acc[mt][2 * u],     a[mt], b[u][0], b[u][1]);
                    mma_f16(acc[mt][2 * u + 1], a[mt], b[u][2], b[u][3]);
                }
        }
    }

    // Epilogue
#pragma unroll
    for (int mt = 0; mt < 4; ++mt) {
#pragma unroll
        for (int nt = 0; nt < 8; ++nt) {
            int row = m0 + wm + mt * 16 + (lane >> 2);
            int col = n0 + wn + nt * 8 + 2 * (lane & 3);
            if (MODE == 1) {
                __half* C = (__half*)Cv;
                float s = (col < DM) ? Q_SCALE : 1.0f;
                *(__half2*)&C[(size_t)row * N + col] =
                    __floats2half2_rn(acc[mt][nt][0] * s, acc[mt][nt][1] * s);
                *(__half2*)&C[(size_t)(row + 8) * N + col] =
                    __floats2half2_rn(acc[mt][nt][2] * s, acc[mt][nt][3] * s);
            } else {
                float* C = (float*)Cv;
                *(float2*)&C[(size_t)row * N + col] =
                    make_float2(acc[mt][nt][0], acc[mt][nt][1]);
                *(float2*)&C[(size_t)(row + 8) * N + col] =
                    make_float2(acc[mt][nt][2], acc[mt][nt][3]);
            }
        }
    }
}

// ---------------------------------------------------------------------------
// Flash attention, fp16 mma + ldmatrix, 128-col KV pairs, f16x2 exp2 path.
// Block = (64-row Q tile, head), 128 threads / 4 warps.
// ---------------------------------------------------------------------------
constexpr int F_STRIDE = 144;
constexpr int F_TILE   = 64 * F_STRIDE;
constexpr int F_PAIR   = 2 * F_TILE;
constexpr int FL_SMEM  = F_TILE + 4 * F_PAIR;  // 82944 B

__global__ __launch_bounds__(128) void flash_f16(
    const __half* __restrict__ qkv, __half* __restrict__ out)
{
    extern __shared__ char fsm[];
    char* Qs  = fsm;
    char* KsB = fsm + F_TILE;
    char* VsB = fsm + F_TILE + 2 * F_PAIR;

    const int tid  = threadIdx.x;
    const int lane = tid & 31;
    const int w    = tid >> 5;
    const int h    = blockIdx.y;
    const int qt   = (int)gridDim.x - 1 - (int)blockIdx.x;  // heavy first
    const int q0   = qt * 64;
    const int pmax = qt >> 1;

    const int grp = lane >> 3, rw = lane & 7;
    const int q_row = (grp & 1) * 8 + rw;
    const int q_byt = (grp >> 1) * 16;
    const int k_row = (grp >> 1) * 8 + rw;
    const int k_byt = (grp & 1) * 16;
    const int v_row = (grp & 1) * 8 + rw;
    const int v_byt = (grp >> 1) * 16;

    const char* qg = (const char*)(qkv + (size_t)q0 * QKV_N + h * HD);

    auto issue_pair = [&](int p, int buf) {
        char* Ks = KsB + buf * F_PAIR;
        char* Vs = VsB + buf * F_PAIR;
#pragma unroll
        for (int half = 0; half < 2; ++half) {
            int tile = 2 * p + half;
            if (tile > S_LEN / 64 - 1) tile = S_LEN / 64 - 1;
            const char* kg = (const char*)(qkv + (size_t)(tile * 64) * QKV_N + DM + h * HD);
            const char* vg = kg + DM * 2;
#pragma unroll
            for (int pp = 0; pp < 4; ++pp) {
                int idx = tid + pp * 128;
                int row = idx >> 3;
                int seg = (idx & 7) * 16;
                cp_async16(Ks + (half * 64 + row) * F_STRIDE + seg,
                           kg + (size_t)row * QKV_N * 2 + seg);
                cp_async16(Vs + (half * 64 + row) * F_STRIDE + seg,
                           vg + (size_t)row * QKV_N * 2 + seg);
            }
        }
        cp_commit();
    };

    // Prologue
    {
#pragma unroll
        for (int pp = 0; pp < 4; ++pp) {
            int idx = tid + pp * 128;
            int row = idx >> 3;
            int seg = (idx & 7) * 16;
            cp_async16(Qs + row * F_STRIDE + seg, qg + (size_t)row * QKV_N * 2 + seg);
        }
        cp_commit();
    }
    issue_pair(0, 0);

    const int r  = (lane >> 2);
    const int qr = w * 16 + r;
    uint32_t Qf[4][4];
    float m_i[2] = {-1e30f, -1e30f};
    float l_i[2] = {0.f, 0.f};
    float oacc[8][4];
#pragma unroll
    for (int n = 0; n < 8; ++n)
#pragma unroll
        for (int c = 0; c < 4; ++c) oacc[n][c] = 0.f;

    const uint32_t q_base = smem_u32(Qs);

    for (int p = 0; p <= pmax; ++p) {
        cp_wait<0>();
        __syncthreads();
        if (p + 1 <= pmax) issue_pair(p + 1, (p + 1) & 1);

        if (p == 0) {
#pragma unroll
            for (int ks = 0; ks < 4; ++ks)
                ldmx4(Qf[ks], q_base + (w * 16 + q_row) * F_STRIDE + ks * 32 + q_byt);
        }

        const uint32_t k_base = smem_u32(KsB + (p & 1) * F_PAIR);
        const uint32_t v_base = smem_u32(VsB + (p & 1) * F_PAIR);

        // S = Q K^T over 128 cols
        float sacc[16][4];
#pragma unroll
        for (int n = 0; n < 16; ++n)
#pragma unroll
            for (int c = 0; c < 4; ++c) sacc[n][c] = 0.f;

#pragma unroll
        for (int ks = 0; ks < 4; ++ks) {
#pragma unroll
            for (int u = 0; u < 8; ++u) {
                uint32_t b[4];
                ldmx4(b, k_base + (u * 16 + k_row) * F_STRIDE + ks * 32 + k_byt);
                mma_f16(sacc[2 * u],     Qf[ks], b[0], b[1]);
                mma_f16(sacc[2 * u + 1], Qf[ks], b[2], b[3]);
            }
        }

        // Causal mask — only the last pair straddles/exceeds the diagonal
        if (p == pmax) {
#pragma unroll
            for (int nt = 0; nt < 16; ++nt) {
#pragma unroll
                for (int c = 0; c < 4; ++c) {
                    int col_g = p * 128 + nt * 8 + 2 * (lane & 3) + (c & 1);
                    int row_g = q0 + qr + (c >> 1) * 8;
                    if (col_g > row_g) sacc[nt][c] = -1e30f;
                }
            }
        }

        // Online softmax (exp2 domain), P computed via ex2.approx.f16x2.
        float alpha[2];
        uint32_t pa[8][4];
#pragma unroll
        for (int half = 0; half < 2; ++half) {
            float mx = -1e30f;
#pragma unroll
            for (int nt = 0; nt < 16; ++nt) {
                mx = fmaxf(mx, sacc[nt][half * 2]);
                mx = fmaxf(mx, sacc[nt][half * 2 + 1]);
            }
            mx = fmaxf(mx, __shfl_xor_sync(0xffffffffu, mx, 1, 4));
            mx = fmaxf(mx, __shfl_xor_sync(0xffffffffu, mx, 2, 4));
            float mnew = fmaxf(m_i[half], mx);
            alpha[half] = ex2(m_i[half] - mnew);
            m_i[half] = mnew;
            float rs = 0.f;
#pragma unroll
            for (int nt = 0; nt < 16; ++nt) {
                uint32_t hp = h2ex2(f2h2(sacc[nt][half * 2]     - mnew,
                                         sacc[nt][half * 2 + 1] - mnew));
                pa[nt >> 1][(nt & 1) * 2 + half] = hp;   // PV A-fragment slot
                float2 f = __half22float2(*(__half2*)&hp);
                rs += f.x + f.y;
            }
            rs += __shfl_xor_sync(0xffffffffu, rs, 1, 4);
            rs += __shfl_xor_sync(0xffffffffu, rs, 2, 4);
            l_i[half] = l_i[half] * alpha[half] + rs;
        }

#pragma unroll
        for (int nt = 0; nt < 8; ++nt) {
            oacc[nt][0] *= alpha[0]; oacc[nt][1] *= alpha[0];
            oacc[nt][2] *= alpha[1]; oacc[nt][3] *= alpha[1];
        }

        // O += P V  (V via ldmatrix.trans)
#pragma unroll
        for (int ks = 0; ks < 8; ++ks) {
#pragma unroll
            for (int u = 0; u < 4; ++u) {
                uint32_t b[4];
                ldmx4t(b, v_base + (ks * 16 + v_row) * F_STRIDE + u * 32 + v_byt);
                mma_f16(oacc[2 * u],     pa[ks], b[0], b[1]);
                mma_f16(oacc[2 * u + 1], pa[ks], b[2], b[3]);
            }
        }
    }

    // Epilogue
    float inv0 = 1.f / l_i[0];
    float inv1 = 1.f / l_i[1];
#pragma unroll
    for (int nt = 0; nt < 8; ++nt) {
        int col = h * HD + nt * 8 + 2 * (lane & 3);
        int row = q0 + qr;
        *(__half2*)&out[(size_t)row * DM + col] =
            __floats2half2_rn(oacc[nt][0] * inv0, oacc[nt][1] * inv0);
        *(__half2*)&out[(size_t)(row + 8) * DM + col] =
            __floats2half2_rn(oacc[nt][2] * inv1, oacc[nt][3] * inv1);
    }
}

// ---------------------------------------------------------------------------
// Launch
// ---------------------------------------------------------------------------
extern "C" void kernel_launch(void* const* d_in, const int* in_sizes, int n_in,
                              void* d_out, int out_size)
{
    const float* x     = (const float*)d_in[0];
    const float* w_qkv = (const float*)d_in[1];
    const float* w_out = (const float*)d_in[2];
    float* out = (float*)d_out;

    __half *xr, *wqkvr, *woutr, *qkvp, *attp;
    cudaGetSymbolAddress((void**)&xr,    g_x);
    cudaGetSymbolAddress((void**)&wqkvr, g_wqkv);
    cudaGetSymbolAddress((void**)&woutr, g_wout);
    cudaGetSymbolAddress((void**)&qkvp,  g_qkv);
    cudaGetSymbolAddress((void**)&attp,  g_att);

    cudaFuncSetAttribute(gemm_f16<1>,
                         cudaFuncAttributeMaxDynamicSharedMemorySize, GEMM_SMEM);
    cudaFuncSetAttribute(gemm_f16<0>,
                         cudaFuncAttributeMaxDynamicSharedMemorySize, GEMM_SMEM);
    cudaFuncSetAttribute(flash_f16,
                         cudaFuncAttributeMaxDynamicSharedMemorySize, FL_SMEM);

    // 0) fp32 -> fp16 inputs, single launch
    {
        int na4 = S_LEN * DM / 4;
        int nb4 = QKV_N * DM / 4;
        int nc4 = DM * DM / 4;
        int ntot = na4 + nb4 + nc4;
        cvt_all_kernel<<<(ntot + 255) / 256, 256>>>(x, xr, na4, w_qkv, wqkvr, nb4,
                                                    w_out, woutr, nc4);
    }
    // 1) QKV projection (fp16 out; q scaled by 0.125*log2e)
    {
        dim3 grid(QKV_N / 128, S_LEN / 128);
        gemm_f16<1><<<grid, 128, GEMM_SMEM>>>(xr, wqkvr, qkvp, S_LEN, QKV_N, DM);
    }
    // 2) Flash attention (fp16 out)
    {
        dim3 grid(S_LEN / 64, NH);
        flash_f16<<<grid, 128, FL_SMEM>>>(qkvp, attp);
    }
    // 3) Output projection (fp32 out)
    {
        dim3 grid(DM / 128, S_LEN / 128);
        gemm_f16<0><<<grid, 128, GEMM_SMEM>>>(attp, woutr, out, S_LEN, DM, DM);
    }
}

// round 12
// speedup vs baseline: 2.7314x; 1.0620x over previous
#include <cuda_runtime.h>
#include <cuda_fp16.h>
#include <cstdint>

// Problem constants
constexpr int S_LEN = 4096;
constexpr int DM    = 1024;
constexpr int NH    = 16;
constexpr int HD    = 64;
constexpr int QKV_N = 3 * DM;  // 3072

// q section scaled by 0.125*log2(e): softmax computed in exp2 domain.
constexpr float Q_SCALE = 0.125f * 1.4426950408889634f;

// Scratch device globals — fp16
__device__ __half g_x   [(size_t)S_LEN * DM];
__device__ __half g_wqkv[(size_t)QKV_N * DM];
__device__ __half g_wout[(size_t)DM * DM];
__device__ __half g_qkv [(size_t)S_LEN * QKV_N];
__device__ __half g_att [(size_t)S_LEN * DM];

// ---------------------------------------------------------------------------
// Helpers
// ---------------------------------------------------------------------------
__device__ __forceinline__ void cp_async16(void* smem_dst, const void* gmem_src) {
    uint32_t s = (uint32_t)__cvta_generic_to_shared(smem_dst);
    asm volatile("cp.async.cg.shared.global [%0], [%1], 16;" :: "r"(s), "l"(gmem_src));
}
__device__ __forceinline__ void cp_commit() {
    asm volatile("cp.async.commit_group;");
}
template<int N>
__device__ __forceinline__ void cp_wait() {
    asm volatile("cp.async.wait_group %0;" :: "n"(N));
}
__device__ __forceinline__ uint32_t smem_u32(const void* p) {
    return (uint32_t)__cvta_generic_to_shared(p);
}
__device__ __forceinline__ float ex2(float x) {
    float y;
    asm("ex2.approx.ftz.f32 %0, %1;" : "=f"(y) : "f"(x));
    return y;
}
__device__ __forceinline__ uint32_t h2ex2(uint32_t x) {
    uint32_t y;
    asm("ex2.approx.f16x2 %0, %1;" : "=r"(y) : "r"(x));
    return y;
}
__device__ __forceinline__ void ldmx4(uint32_t r[4], uint32_t a) {
    asm volatile("ldmatrix.sync.aligned.m8n8.x4.shared.b16 {%0,%1,%2,%3}, [%4];"
                 : "=r"(r[0]), "=r"(r[1]), "=r"(r[2]), "=r"(r[3]) : "r"(a));
}
__device__ __forceinline__ void ldmx4t(uint32_t r[4], uint32_t a) {
    asm volatile("ldmatrix.sync.aligned.m8n8.x4.trans.shared.b16 {%0,%1,%2,%3}, [%4];"
                 : "=r"(r[0]), "=r"(r[1]), "=r"(r[2]), "=r"(r[3]) : "r"(a));
}
__device__ __forceinline__ void mma_f16(float c[4], const uint32_t a[4],
                                        uint32_t b0, uint32_t b1) {
    asm volatile(
        "mma.sync.aligned.m16n8k16.row.col.f32.f16.f16.f32 "
        "{%0,%1,%2,%3}, {%4,%5,%6,%7}, {%8,%9}, {%0,%1,%2,%3};"
        : "+f"(c[0]), "+f"(c[1]), "+f"(c[2]), "+f"(c[3])
        : "r"(a[0]), "r"(a[1]), "r"(a[2]), "r"(a[3]), "r"(b0), "r"(b1));
}
__device__ __forceinline__ uint32_t f2h2(float x, float y) {
    __half2 h = __floats2half2_rn(x, y);
    return *(uint32_t*)&h;
}

// ---------------------------------------------------------------------------
// fp32 -> fp16 conversion pre-pass: all three tensors, ONE launch
// ---------------------------------------------------------------------------
__global__ void cvt_all_kernel(const float* __restrict__ a, __half* __restrict__ oa, int na4,
                               const float* __restrict__ b, __half* __restrict__ ob, int nb4,
                               const float* __restrict__ c, __half* __restrict__ oc, int nc4) {
    int j = blockIdx.x * blockDim.x + threadIdx.x;
    const float* in; __half* out;
    if (j < na4) { in = a; out = oa; }
    else {
        j -= na4;
        if (j < nb4) { in = b; out = ob; }
        else {
            j -= nb4;
            if (j >= nc4) return;
            in = c; out = oc;
        }
    }
    float4 v = ((const float4*)in)[j];
    ((__half2*)out)[j * 2 + 0] = __floats2half2_rn(v.x, v.y);
    ((__half2*)out)[j * 2 + 1] = __floats2half2_rn(v.z, v.w);
}

// ---------------------------------------------------------------------------
// FP16 GEMM: C[M,N] = A[M,K]*B[N,K]^T, fp32 accum. Block 128x128,
// 128 threads / 4 warps, 64x64 warp tiles.
// K-chunk 64, 2-stage cp.async double buffer, ONE barrier per 64-K
// (half the barrier count of the K-32 pipeline; smem 72 KB -> 3 blocks/SM,
//  matching the register-derived occupancy cap).
// MODE 1: fp16 out; q cols (col<DM) scaled by Q_SCALE.  MODE 0: fp32 out.
// ---------------------------------------------------------------------------
constexpr int G_STRIDE = 144;                  // bytes per smem row (64 halves + pad)
constexpr int G_STAGE  = 128 * G_STRIDE;       // 18432 B per operand stage
constexpr int GEMM_SMEM = 2 * 2 * G_STAGE;     // 73728 B

template<int MODE>
__global__ __launch_bounds__(128) void gemm_f16(
    const __half* __restrict__ A, const __half* __restrict__ B,
    void* __restrict__ Cv, int M, int N, int K)
{
    extern __shared__ char sm[];
    char* AsBase = sm;
    char* BsBase = sm + 2 * G_STAGE;

    const int tid  = threadIdx.x;
    const int lane = tid & 31;
    const int wid  = tid >> 5;
    const int wm   = (wid >> 1) * 64;
    const int wn   = (wid & 1) * 64;
    const int m0   = blockIdx.y * 128;
    const int n0   = blockIdx.x * 128;
    const int NI   = K / 64;

    const int grp = lane >> 3, rw = lane & 7;
    const int a_row = (grp & 1) * 8 + rw;
    const int a_byt = (grp >> 1) * 16;
    const int b_row = (grp >> 1) * 8 + rw;
    const int b_byt = (grp & 1) * 16;

    auto issue_tile = [&](int it, int buf) {
        const char* Ag = (const char*)(A + (size_t)m0 * K + it * 64);
        const char* Bg = (const char*)(B + (size_t)n0 * K + it * 64);
        char* As = AsBase + buf * G_STAGE;
        char* Bs = BsBase + buf * G_STAGE;
#pragma unroll
        for (int p = 0; p < 8; ++p) {
            int idx = tid + p * 128;            // 0..1023 (128 rows x 8 segs)
            int row = idx >> 3;
            int seg = (idx & 7) * 16;
            cp_async16(As + row * G_STRIDE + seg, Ag + (size_t)row * K * 2 + seg);
            cp_async16(Bs + row * G_STRIDE + seg, Bg + (size_t)row * K * 2 + seg);
        }
        cp_commit();
    };

    float acc[4][8][4];
#pragma unroll
    for (int i = 0; i < 4; ++i)
#pragma unroll
        for (int j = 0; j < 8; ++j)
#pragma unroll
            for (int c = 0; c < 4; ++c) acc[i][j][c] = 0.f;

    issue_tile(0, 0);

    for (int it = 0; it < NI; ++it) {
        cp_wait<0>();
        __syncthreads();                        // one barrier per 64-K
        if (it + 1 < NI) issue_tile(it + 1, (it + 1) & 1);

        const uint32_t a_base = smem_u32(AsBase + (it & 1) * G_STAGE);
        const uint32_t b_base = smem_u32(BsBase + (it & 1) * G_STAGE);

#pragma unroll
        for (int ks = 0; ks < 4; ++ks) {
            uint32_t a[4][4], b[4][4];
#pragma unroll
            for (int mt = 0; mt < 4; ++mt)
                ldmx4(a[mt], a_base + (wm + mt * 16 + a_row) * G_STRIDE
                              + ks * 32 + a_byt);
#pragma unroll
            for (int u = 0; u < 4; ++u)
                ldmx4(b[u], b_base + (wn + u * 16 + b_row) * G_STRIDE
                             + ks * 32 + b_byt);
#pragma unroll
            for (int mt = 0; mt < 4; ++mt)
#pragma unroll
                for (int u = 0; u < 4; ++u) {
                    mma_f16(acc[mt][2 * u],     a[mt], b[u][0], b[u][1]);
                    mma_f16(acc[mt][2 * u + 1], a[mt], b[u][2], b[u][3]);
                }
        }
    }

    // Epilogue
#pragma unroll
    for (int mt = 0; mt < 4; ++mt) {
#pragma unroll
        for (int nt = 0; nt < 8; ++nt) {
            int row = m0 + wm + mt * 16 + (lane >> 2);
            int col = n0 + wn + nt * 8 + 2 * (lane & 3);
            if (MODE == 1) {
                __half* C = (__half*)Cv;
                float s = (col < DM) ? Q_SCALE : 1.0f;
                *(__half2*)&C[(size_t)row * N + col] =
                    __floats2half2_rn(acc[mt][nt][0] * s, acc[mt][nt][1] * s);
                *(__half2*)&C[(size_t)(row + 8) * N + col] =
                    __floats2half2_rn(acc[mt][nt][2] * s, acc[mt][nt][3] * s);
            } else {
                float* C = (float*)Cv;
                *(float2*)&C[(size_t)row * N + col] =
                    make_float2(acc[mt][nt][0], acc[mt][nt][1]);
                *(float2*)&C[(size_t)(row + 8) * N + col] =
                    make_float2(acc[mt][nt][2], acc[mt][nt][3]);
            }
        }
    }
}

// ---------------------------------------------------------------------------
// Flash attention, fp16 mma + ldmatrix, 128-col KV pairs, f16x2 exp2 path.
// Block = (64-row Q tile, head), 128 threads / 4 warps.  (unchanged from R11)
// ---------------------------------------------------------------------------
constexpr int F_STRIDE = 144;
constexpr int F_TILE   = 64 * F_STRIDE;
constexpr int F_PAIR   = 2 * F_TILE;
constexpr int FL_SMEM  = F_TILE + 4 * F_PAIR;  // 82944 B

__global__ __launch_bounds__(128) void flash_f16(
    const __half* __restrict__ qkv, __half* __restrict__ out)
{
    extern __shared__ char fsm[];
    char* Qs  = fsm;
    char* KsB = fsm + F_TILE;
    char* VsB = fsm + F_TILE + 2 * F_PAIR;

    const int tid  = threadIdx.x;
    const int lane = tid & 31;
    const int w    = tid >> 5;
    const int h    = blockIdx.y;
    const int qt   = (int)gridDim.x - 1 - (int)blockIdx.x;  // heavy first
    const int q0   = qt * 64;
    const int pmax = qt >> 1;

    const int grp = lane >> 3, rw = lane & 7;
    const int q_row = (grp & 1) * 8 + rw;
    const int q_byt = (grp >> 1) * 16;
    const int k_row = (grp >> 1) * 8 + rw;
    const int k_byt = (grp & 1) * 16;
    const int v_row = (grp & 1) * 8 + rw;
    const int v_byt = (grp >> 1) * 16;

    const char* qg = (const char*)(qkv + (size_t)q0 * QKV_N + h * HD);

    auto issue_pair = [&](int p, int buf) {
        char* Ks = KsB + buf * F_PAIR;
        char* Vs = VsB + buf * F_PAIR;
#pragma unroll
        for (int half = 0; half < 2; ++half) {
            int tile = 2 * p + half;
            if (tile > S_LEN / 64 - 1) tile = S_LEN / 64 - 1;
            const char* kg = (const char*)(qkv + (size_t)(tile * 64) * QKV_N + DM + h * HD);
            const char* vg = kg + DM * 2;
#pragma unroll
            for (int pp = 0; pp < 4; ++pp) {
                int idx = tid + pp * 128;
                int row = idx >> 3;
                int seg = (idx & 7) * 16;
                cp_async16(Ks + (half * 64 + row) * F_STRIDE + seg,
                           kg + (size_t)row * QKV_N * 2 + seg);
                cp_async16(Vs + (half * 64 + row) * F_STRIDE + seg,
                           vg + (size_t)row * QKV_N * 2 + seg);
            }
        }
        cp_commit();
    };

    // Prologue
    {
#pragma unroll
        for (int pp = 0; pp < 4; ++pp) {
            int idx = tid + pp * 128;
            int row = idx >> 3;
            int seg = (idx & 7) * 16;
            cp_async16(Qs + row * F_STRIDE + seg, qg + (size_t)row * QKV_N * 2 + seg);
        }
        cp_commit();
    }
    issue_pair(0, 0);

    const int r  = (lane >> 2);
    const int qr = w * 16 + r;
    uint32_t Qf[4][4];
    float m_i[2] = {-1e30f, -1e30f};
    float l_i[2] = {0.f, 0.f};
    float oacc[8][4];
#pragma unroll
    for (int n = 0; n < 8; ++n)
#pragma unroll
        for (int c = 0; c < 4; ++c) oacc[n][c] = 0.f;

    const uint32_t q_base = smem_u32(Qs);

    for (int p = 0; p <= pmax; ++p) {
        cp_wait<0>();
        __syncthreads();
        if (p + 1 <= pmax) issue_pair(p + 1, (p + 1) & 1);

        if (p == 0) {
#pragma unroll
            for (int ks = 0; ks < 4; ++ks)
                ldmx4(Qf[ks], q_base + (w * 16 + q_row) * F_STRIDE + ks * 32 + q_byt);
        }

        const uint32_t k_base = smem_u32(KsB + (p & 1) * F_PAIR);
        const uint32_t v_base = smem_u32(VsB + (p & 1) * F_PAIR);

        // S = Q K^T over 128 cols
        float sacc[16][4];
#pragma unroll
        for (int n = 0; n < 16; ++n)
#pragma unroll
            for (int c = 0; c < 4; ++c) sacc[n][c] = 0.f;

#pragma unroll
        for (int ks = 0; ks < 4; ++ks) {
#pragma unroll
            for (int u = 0; u < 8; ++u) {
                uint32_t b[4];
                ldmx4(b, k_base + (u * 16 + k_row) * F_STRIDE + ks * 32 + k_byt);
                mma_f16(sacc[2 * u],     Qf[ks], b[0], b[1]);
                mma_f16(sacc[2 * u + 1], Qf[ks], b[2], b[3]);
            }
        }

        // Causal mask — only the last pair straddles/exceeds the diagonal
        if (p == pmax) {
#pragma unroll
            for (int nt = 0; nt < 16; ++nt) {
#pragma unroll
                for (int c = 0; c < 4; ++c) {
                    int col_g = p * 128 + nt * 8 + 2 * (lane & 3) + (c & 1);
                    int row_g = q0 + qr + (c >> 1) * 8;
                    if (col_g > row_g) sacc[nt][c] = -1e30f;
                }
            }
        }

        // Online softmax (exp2 domain), P via ex2.approx.f16x2.
        float alpha[2];
        uint32_t pa[8][4];
#pragma unroll
        for (int half = 0; half < 2; ++half) {
            float mx = -1e30f;
#pragma unroll
            for (int nt = 0; nt < 16; ++nt) {
                mx = fmaxf(mx, sacc[nt][half * 2]);
                mx = fmaxf(mx, sacc[nt][half * 2 + 1]);
            }
            mx = fmaxf(mx, __shfl_xor_sync(0xffffffffu, mx, 1, 4));
            mx = fmaxf(mx, __shfl_xor_sync(0xffffffffu, mx, 2, 4));
            float mnew = fmaxf(m_i[half], mx);
            alpha[half] = ex2(m_i[half] - mnew);
            m_i[half] = mnew;
            float rs = 0.f;
#pragma unroll
            for (int nt = 0; nt < 16; ++nt) {
                uint32_t hp = h2ex2(f2h2(sacc[nt][half * 2]     - mnew,
                                         sacc[nt][half * 2 + 1] - mnew));
                pa[nt >> 1][(nt & 1) * 2 + half] = hp;
                float2 f = __half22float2(*(__half2*)&hp);
                rs += f.x + f.y;
            }
            rs += __shfl_xor_sync(0xffffffffu, rs, 1, 4);
            rs += __shfl_xor_sync(0xffffffffu, rs, 2, 4);
            l_i[half] = l_i[half] * alpha[half] + rs;
        }

#pragma unroll
        for (int nt = 0; nt < 8; ++nt) {
            oacc[nt][0] *= alpha[0]; oacc[nt][1] *= alpha[0];
            oacc[nt][2] *= alpha[1]; oacc[nt][3] *= alpha[1];
        }

        // O += P V  (V via ldmatrix.trans)
#pragma unroll
        for (int ks = 0; ks < 8; ++ks) {
#pragma unroll
            for (int u = 0; u < 4; ++u) {
                uint32_t b[4];
                ldmx4t(b, v_base + (ks * 16 + v_row) * F_STRIDE + u * 32 + v_byt);
                mma_f16(oacc[2 * u],     pa[ks], b[0], b[1]);
                mma_f16(oacc[2 * u + 1], pa[ks], b[2], b[3]);
            }
        }
    }

    // Epilogue
    float inv0 = 1.f / l_i[0];
    float inv1 = 1.f / l_i[1];
#pragma unroll
    for (int nt = 0; nt < 8; ++nt) {
        int col = h * HD + nt * 8 + 2 * (lane & 3);
        int row = q0 + qr;
        *(__half2*)&out[(size_t)row * DM + col] =
            __floats2half2_rn(oacc[nt][0] * inv0, oacc[nt][1] * inv0);
        *(__half2*)&out[(size_t)(row + 8) * DM + col] =
            __floats2half2_rn(oacc[nt][2] * inv1, oacc[nt][3] * inv1);
    }
}

// ---------------------------------------------------------------------------
// Launch
// ---------------------------------------------------------------------------
extern "C" void kernel_launch(void* const* d_in, const int* in_sizes, int n_in,
                              void* d_out, int out_size)
{
    const float* x     = (const float*)d_in[0];
    const float* w_qkv = (const float*)d_in[1];
    const float* w_out = (const float*)d_in[2];
    float* out = (float*)d_out;

    __half *xr, *wqkvr, *woutr, *qkvp, *attp;
    cudaGetSymbolAddress((void**)&xr,    g_x);
    cudaGetSymbolAddress((void**)&wqkvr, g_wqkv);
    cudaGetSymbolAddress((void**)&woutr, g_wout);
    cudaGetSymbolAddress((void**)&qkvp,  g_qkv);
    cudaGetSymbolAddress((void**)&attp,  g_att);

    cudaFuncSetAttribute(gemm_f16<1>,
                         cudaFuncAttributeMaxDynamicSharedMemorySize, GEMM_SMEM);
    cudaFuncSetAttribute(gemm_f16<0>,
                         cudaFuncAttributeMaxDynamicSharedMemorySize, GEMM_SMEM);
    cudaFuncSetAttribute(flash_f16,
                         cudaFuncAttributeMaxDynamicSharedMemorySize, FL_SMEM);

    // 0) fp32 -> fp16 inputs, single launch
    {
        int na4 = S_LEN * DM / 4;
        int nb4 = QKV_N * DM / 4;
        int nc4 = DM * DM / 4;
        int ntot = na4 + nb4 + nc4;
        cvt_all_kernel<<<(ntot + 255) / 256, 256>>>(x, xr, na4, w_qkv, wqkvr, nb4,
                                                    w_out, woutr, nc4);
    }
    // 1) QKV projection (fp16 out; q scaled by 0.125*log2e)
    {
        dim3 grid(QKV_N / 128, S_LEN / 128);
        gemm_f16<1><<<grid, 128, GEMM_SMEM>>>(xr, wqkvr, qkvp, S_LEN, QKV_N, DM);
    }
    // 2) Flash attention (fp16 out)
    {
        dim3 grid(S_LEN / 64, NH);
        flash_f16<<<grid, 128, FL_SMEM>>>(qkvp, attp);
    }
    // 3) Output projection (fp32 out)
    {
        dim3 grid(DM / 128, S_LEN / 128);
        gemm_f16<0><<<grid, 128, GEMM_SMEM>>>(attp, woutr, out, S_LEN, DM, DM);
    }
}

// round 13
// speedup vs baseline: 2.7438x; 1.0045x over previous
#include <cuda_runtime.h>
#include <cuda_fp16.h>
#include <cstdint>

// Problem constants
constexpr int S_LEN = 4096;
constexpr int DM    = 1024;
constexpr int NH    = 16;
constexpr int HD    = 64;
constexpr int QKV_N = 3 * DM;  // 3072

// q section scaled by 0.125*log2(e): softmax computed in exp2 domain.
constexpr float Q_SCALE = 0.125f * 1.4426950408889634f;

// Scratch device globals — fp16
__device__ __half g_x   [(size_t)S_LEN * DM];
__device__ __half g_wqkv[(size_t)QKV_N * DM];
__device__ __half g_wout[(size_t)DM * DM];
__device__ __half g_qkv [(size_t)S_LEN * QKV_N];
__device__ __half g_att [(size_t)S_LEN * DM];

// ---------------------------------------------------------------------------
// Helpers
// ---------------------------------------------------------------------------
__device__ __forceinline__ void cp_async16(void* smem_dst, const void* gmem_src) {
    uint32_t s = (uint32_t)__cvta_generic_to_shared(smem_dst);
    asm volatile("cp.async.cg.shared.global [%0], [%1], 16;" :: "r"(s), "l"(gmem_src));
}
__device__ __forceinline__ void cp_commit() {
    asm volatile("cp.async.commit_group;");
}
template<int N>
__device__ __forceinline__ void cp_wait() {
    asm volatile("cp.async.wait_group %0;" :: "n"(N));
}
__device__ __forceinline__ uint32_t smem_u32(const void* p) {
    return (uint32_t)__cvta_generic_to_shared(p);
}
__device__ __forceinline__ float ex2(float x) {
    float y;
    asm("ex2.approx.ftz.f32 %0, %1;" : "=f"(y) : "f"(x));
    return y;
}
__device__ __forceinline__ uint32_t h2ex2(uint32_t x) {
    uint32_t y;
    asm("ex2.approx.f16x2 %0, %1;" : "=r"(y) : "r"(x));
    return y;
}
__device__ __forceinline__ void ldmx4(uint32_t r[4], uint32_t a) {
    asm volatile("ldmatrix.sync.aligned.m8n8.x4.shared.b16 {%0,%1,%2,%3}, [%4];"
                 : "=r"(r[0]), "=r"(r[1]), "=r"(r[2]), "=r"(r[3]) : "r"(a));
}
__device__ __forceinline__ void ldmx4t(uint32_t r[4], uint32_t a) {
    asm volatile("ldmatrix.sync.aligned.m8n8.x4.trans.shared.b16 {%0,%1,%2,%3}, [%4];"
                 : "=r"(r[0]), "=r"(r[1]), "=r"(r[2]), "=r"(r[3]) : "r"(a));
}
__device__ __forceinline__ void mma_f16(float c[4], const uint32_t a[4],
                                        uint32_t b0, uint32_t b1) {
    asm volatile(
        "mma.sync.aligned.m16n8k16.row.col.f32.f16.f16.f32 "
        "{%0,%1,%2,%3}, {%4,%5,%6,%7}, {%8,%9}, {%0,%1,%2,%3};"
        : "+f"(c[0]), "+f"(c[1]), "+f"(c[2]), "+f"(c[3])
        : "r"(a[0]), "r"(a[1]), "r"(a[2]), "r"(a[3]), "r"(b0), "r"(b1));
}
__device__ __forceinline__ uint32_t f2h2(float x, float y) {
    __half2 h = __floats2half2_rn(x, y);
    return *(uint32_t*)&h;
}

// ---------------------------------------------------------------------------
// fp32 -> fp16 conversion pre-pass: all three tensors, ONE launch
// ---------------------------------------------------------------------------
__global__ void cvt_all_kernel(const float* __restrict__ a, __half* __restrict__ oa, int na4,
                               const float* __restrict__ b, __half* __restrict__ ob, int nb4,
                               const float* __restrict__ c, __half* __restrict__ oc, int nc4) {
    int j = blockIdx.x * blockDim.x + threadIdx.x;
    const float* in; __half* out;
    if (j < na4) { in = a; out = oa; }
    else {
        j -= na4;
        if (j < nb4) { in = b; out = ob; }
        else {
            j -= nb4;
            if (j >= nc4) return;
            in = c; out = oc;
        }
    }
    float4 v = ((const float4*)in)[j];
    ((__half2*)out)[j * 2 + 0] = __floats2half2_rn(v.x, v.y);
    ((__half2*)out)[j * 2 + 1] = __floats2half2_rn(v.z, v.w);
}

// ---------------------------------------------------------------------------
// FP16 GEMM: C[M,N] = A[M,K]*B[N,K]^T, fp32 accum.
// Block 64x128 (BM=64, BN=128), 128 threads / 4 warps, 32x64 warp tiles.
// K-chunk 64, 2-stage cp.async double buffer, one barrier per 64-K.
// Smem 55296 B -> 4 blocks/SM; ~100 regs -> 16 warps/SM.
// MODE 1: fp16 out; q cols (col<DM) scaled by Q_SCALE.  MODE 0: fp32 out.
// ---------------------------------------------------------------------------
constexpr int G_STRIDE  = 144;                   // bytes per smem row
constexpr int GA_STAGE  = 64 * G_STRIDE;         // 9216 B
constexpr int GB_STAGE  = 128 * G_STRIDE;        // 18432 B
constexpr int GEMM_SMEM = 2 * (GA_STAGE + GB_STAGE);  // 55296 B

template<int MODE>
__global__ __launch_bounds__(128) void gemm_f16(
    const __half* __restrict__ A, const __half* __restrict__ B,
    void* __restrict__ Cv, int M, int N, int K)
{
    extern __shared__ char sm[];
    char* AsBase = sm;                      // 2 * GA_STAGE
    char* BsBase = sm + 2 * GA_STAGE;       // 2 * GB_STAGE

    const int tid  = threadIdx.x;
    const int lane = tid & 31;
    const int wid  = tid >> 5;
    const int wm   = (wid >> 1) * 32;       // 0 / 32
    const int wn   = (wid & 1) * 64;        // 0 / 64
    const int m0   = blockIdx.y * 64;
    const int n0   = blockIdx.x * 128;
    const int NI   = K / 64;

    const int grp = lane >> 3, rw = lane & 7;
    const int a_row = (grp & 1) * 8 + rw;
    const int a_byt = (grp >> 1) * 16;
    const int b_row = (grp >> 1) * 8 + rw;
    const int b_byt = (grp & 1) * 16;

    auto issue_tile = [&](int it, int buf) {
        const char* Ag = (const char*)(A + (size_t)m0 * K + it * 64);
        const char* Bg = (const char*)(B + (size_t)n0 * K + it * 64);
        char* As = AsBase + buf * GA_STAGE;
        char* Bs = BsBase + buf * GB_STAGE;
#pragma unroll
        for (int p = 0; p < 4; ++p) {       // A: 64 rows x 8 segs = 512
            int idx = tid + p * 128;
            int row = idx >> 3;
            int seg = (idx & 7) * 16;
            cp_async16(As + row * G_STRIDE + seg, Ag + (size_t)row * K * 2 + seg);
        }
#pragma unroll
        for (int p = 0; p < 8; ++p) {       // B: 128 rows x 8 segs = 1024
            int idx = tid + p * 128;
            int row = idx >> 3;
            int seg = (idx & 7) * 16;
            cp_async16(Bs + row * G_STRIDE + seg, Bg + (size_t)row * K * 2 + seg);
        }
        cp_commit();
    };

    float acc[2][8][4];
#pragma unroll
    for (int i = 0; i < 2; ++i)
#pragma unroll
        for (int j = 0; j < 8; ++j)
#pragma unroll
            for (int c = 0; c < 4; ++c) acc[i][j][c] = 0.f;

    issue_tile(0, 0);

    for (int it = 0; it < NI; ++it) {
        cp_wait<0>();
        __syncthreads();                    // one barrier per 64-K
        if (it + 1 < NI) issue_tile(it + 1, (it + 1) & 1);

        const uint32_t a_base = smem_u32(AsBase + (it & 1) * GA_STAGE);
        const uint32_t b_base = smem_u32(BsBase + (it & 1) * GB_STAGE);

#pragma unroll
        for (int ks = 0; ks < 4; ++ks) {
            uint32_t a[2][4], b[4][4];
#pragma unroll
            for (int mt = 0; mt < 2; ++mt)
                ldmx4(a[mt], a_base + (wm + mt * 16 + a_row) * G_STRIDE
                              + ks * 32 + a_byt);
#pragma unroll
            for (int u = 0; u < 4; ++u)
                ldmx4(b[u], b_base + (wn + u * 16 + b_row) * G_STRIDE
                             + ks * 32 + b_byt);
#pragma unroll
            for (int mt = 0; mt < 2; ++mt)
#pragma unroll
                for (int u = 0; u < 4; ++u) {
                    mma_f16(acc[mt][2 * u],     a[mt], b[u][0], b[u][1]);
                    mma_f16(acc[mt][2 * u + 1], a[mt], b[u][2], b[u][3]);
                }
        }
    }

    // Epilogue
#pragma unroll
    for (int mt = 0; mt < 2; ++mt) {
#pragma unroll
        for (int nt = 0; nt < 8; ++nt) {
            int row = m0 + wm + mt * 16 + (lane >> 2);
            int col = n0 + wn + nt * 8 + 2 * (lane & 3);
            if (MODE == 1) {
                __half* C = (__half*)Cv;
                float s = (col < DM) ? Q_SCALE : 1.0f;
                *(__half2*)&C[(size_t)row * N + col] =
                    __floats2half2_rn(acc[mt][nt][0] * s, acc[mt][nt][1] * s);
                *(__half2*)&C[(size_t)(row + 8) * N + col] =
                    __floats2half2_rn(acc[mt][nt][2] * s, acc[mt][nt][3] * s);
            } else {
                float* C = (float*)Cv;
                *(float2*)&C[(size_t)row * N + col] =
                    make_float2(acc[mt][nt][0], acc[mt][nt][1]);
                *(float2*)&C[(size_t)(row + 8) * N + col] =
                    make_float2(acc[mt][nt][2], acc[mt][nt][3]);
            }
        }
    }
}

// ---------------------------------------------------------------------------
// Flash attention, fp16 mma + ldmatrix, 128-col KV pairs, f16x2 exp2 path.
// Block = (64-row Q tile, head), 128 threads / 4 warps.
// R13: ks=0 V fragments prefetched before softmax.
// ---------------------------------------------------------------------------
constexpr int F_STRIDE = 144;
constexpr int F_TILE   = 64 * F_STRIDE;
constexpr int F_PAIR   = 2 * F_TILE;
constexpr int FL_SMEM  = F_TILE + 4 * F_PAIR;  // 82944 B

__global__ __launch_bounds__(128) void flash_f16(
    const __half* __restrict__ qkv, __half* __restrict__ out)
{
    extern __shared__ char fsm[];
    char* Qs  = fsm;
    char* KsB = fsm + F_TILE;
    char* VsB = fsm + F_TILE + 2 * F_PAIR;

    const int tid  = threadIdx.x;
    const int lane = tid & 31;
    const int w    = tid >> 5;
    const int h    = blockIdx.y;
    const int qt   = (int)gridDim.x - 1 - (int)blockIdx.x;  // heavy first
    const int q0   = qt * 64;
    const int pmax = qt >> 1;

    const int grp = lane >> 3, rw = lane & 7;
    const int q_row = (grp & 1) * 8 + rw;
    const int q_byt = (grp >> 1) * 16;
    const int k_row = (grp >> 1) * 8 + rw;
    const int k_byt = (grp & 1) * 16;
    const int v_row = (grp & 1) * 8 + rw;
    const int v_byt = (grp >> 1) * 16;

    const char* qg = (const char*)(qkv + (size_t)q0 * QKV_N + h * HD);

    auto issue_pair = [&](int p, int buf) {
        char* Ks = KsB + buf * F_PAIR;
        char* Vs = VsB + buf * F_PAIR;
#pragma unroll
        for (int half = 0; half < 2; ++half) {
            int tile = 2 * p + half;
            if (tile > S_LEN / 64 - 1) tile = S_LEN / 64 - 1;
            const char* kg = (const char*)(qkv + (size_t)(tile * 64) * QKV_N + DM + h * HD);
            const char* vg = kg + DM * 2;
#pragma unroll
            for (int pp = 0; pp < 4; ++pp) {
                int idx = tid + pp * 128;
                int row = idx >> 3;
                int seg = (idx & 7) * 16;
                cp_async16(Ks + (half * 64 + row) * F_STRIDE + seg,
                           kg + (size_t)row * QKV_N * 2 + seg);
                cp_async16(Vs + (half * 64 + row) * F_STRIDE + seg,
                           vg + (size_t)row * QKV_N * 2 + seg);
            }
        }
        cp_commit();
    };

    // Prologue
    {
#pragma unroll
        for (int pp = 0; pp < 4; ++pp) {
            int idx = tid + pp * 128;
            int row = idx >> 3;
            int seg = (idx & 7) * 16;
            cp_async16(Qs + row * F_STRIDE + seg, qg + (size_t)row * QKV_N * 2 + seg);
        }
        cp_commit();
    }
    issue_pair(0, 0);

    const int r  = (lane >> 2);
    const int qr = w * 16 + r;
    uint32_t Qf[4][4];
    float m_i[2] = {-1e30f, -1e30f};
    float l_i[2] = {0.f, 0.f};
    float oacc[8][4];
#pragma unroll
    for (int n = 0; n < 8; ++n)
#pragma unroll
        for (int c = 0; c < 4; ++c) oacc[n][c] = 0.f;

    const uint32_t q_base = smem_u32(Qs);

    for (int p = 0; p <= pmax; ++p) {
        cp_wait<0>();
        __syncthreads();
        if (p + 1 <= pmax) issue_pair(p + 1, (p + 1) & 1);

        if (p == 0) {
#pragma unroll
            for (int ks = 0; ks < 4; ++ks)
                ldmx4(Qf[ks], q_base + (w * 16 + q_row) * F_STRIDE + ks * 32 + q_byt);
        }

        const uint32_t k_base = smem_u32(KsB + (p & 1) * F_PAIR);
        const uint32_t v_base = smem_u32(VsB + (p & 1) * F_PAIR);

        // S = Q K^T over 128 cols
        float sacc[16][4];
#pragma unroll
        for (int n = 0; n < 16; ++n)
#pragma unroll
            for (int c = 0; c < 4; ++c) sacc[n][c] = 0.f;

#pragma unroll
        for (int ks = 0; ks < 4; ++ks) {
#pragma unroll
            for (int u = 0; u < 8; ++u) {
                uint32_t b[4];
                ldmx4(b, k_base + (u * 16 + k_row) * F_STRIDE + ks * 32 + k_byt);
                mma_f16(sacc[2 * u],     Qf[ks], b[0], b[1]);
                mma_f16(sacc[2 * u + 1], Qf[ks], b[2], b[3]);
            }
        }

        // Prefetch ks=0 V fragments (independent of softmax) — covers PV start
        uint32_t vb0[4][4];
#pragma unroll
        for (int u = 0; u < 4; ++u)
            ldmx4t(vb0[u], v_base + v_row * F_STRIDE + u * 32 + v_byt);

        // Causal mask — only the last pair straddles/exceeds the diagonal
        if (p == pmax) {
#pragma unroll
            for (int nt = 0; nt < 16; ++nt) {
#pragma unroll
                for (int c = 0; c < 4; ++c) {
                    int col_g = p * 128 + nt * 8 + 2 * (lane & 3) + (c & 1);
                    int row_g = q0 + qr + (c >> 1) * 8;
                    if (col_g > row_g) sacc[nt][c] = -1e30f;
                }
            }
        }

        // Online softmax (exp2 domain), P via ex2.approx.f16x2.
        float alpha[2];
        uint32_t pa[8][4];
#pragma unroll
        for (int half = 0; half < 2; ++half) {
            float mx = -1e30f;
#pragma unroll
            for (int nt = 0; nt < 16; ++nt) {
                mx = fmaxf(mx, sacc[nt][half * 2]);
                mx = fmaxf(mx, sacc[nt][half * 2 + 1]);
            }
            mx = fmaxf(mx, __shfl_xor_sync(0xffffffffu, mx, 1, 4));
            mx = fmaxf(mx, __shfl_xor_sync(0xffffffffu, mx, 2, 4));
            float mnew = fmaxf(m_i[half], mx);
            alpha[half] = ex2(m_i[half] - mnew);
            m_i[half] = mnew;
            float rs = 0.f;
#pragma unroll
            for (int nt = 0; nt < 16; ++nt) {
                uint32_t hp = h2ex2(f2h2(sacc[nt][half * 2]     - mnew,
                                         sacc[nt][half * 2 + 1] - mnew));
                pa[nt >> 1][(nt & 1) * 2 + half] = hp;
                float2 f = __half22float2(*(__half2*)&hp);
                rs += f.x + f.y;
            }
            rs += __shfl_xor_sync(0xffffffffu, rs, 1, 4);
            rs += __shfl_xor_sync(0xffffffffu, rs, 2, 4);
            l_i[half] = l_i[half] * alpha[half] + rs;
        }

#pragma unroll
        for (int nt = 0; nt < 8; ++nt) {
            oacc[nt][0] *= alpha[0]; oacc[nt][1] *= alpha[0];
            oacc[nt][2] *= alpha[1]; oacc[nt][3] *= alpha[1];
        }

        // O += P V  (ks=0 from prefetched fragments; rest via ldmatrix.trans)
#pragma unroll
        for (int u = 0; u < 4; ++u) {
            mma_f16(oacc[2 * u],     pa[0], vb0[u][0], vb0[u][1]);
            mma_f16(oacc[2 * u + 1], pa[0], vb0[u][2], vb0[u][3]);
        }
#pragma unroll
        for (int ks = 1; ks < 8; ++ks) {
#pragma unroll
            for (int u = 0; u < 4; ++u) {
                uint32_t b[4];
                ldmx4t(b, v_base + (ks * 16 + v_row) * F_STRIDE + u * 32 + v_byt);
                mma_f16(oacc[2 * u],     pa[ks], b[0], b[1]);
                mma_f16(oacc[2 * u + 1], pa[ks], b[2], b[3]);
            }
        }
    }

    // Epilogue
    float inv0 = 1.f / l_i[0];
    float inv1 = 1.f / l_i[1];
#pragma unroll
    for (int nt = 0; nt < 8; ++nt) {
        int col = h * HD + nt * 8 + 2 * (lane & 3);
        int row = q0 + qr;
        *(__half2*)&out[(size_t)row * DM + col] =
            __floats2half2_rn(oacc[nt][0] * inv0, oacc[nt][1] * inv0);
        *(__half2*)&out[(size_t)(row + 8) * DM + col] =
            __floats2half2_rn(oacc[nt][2] * inv1, oacc[nt][3] * inv1);
    }
}

// ---------------------------------------------------------------------------
// Launch
// ---------------------------------------------------------------------------
extern "C" void kernel_launch(void* const* d_in, const int* in_sizes, int n_in,
                              void* d_out, int out_size)
{
    const float* x     = (const float*)d_in[0];
    const float* w_qkv = (const float*)d_in[1];
    const float* w_out = (const float*)d_in[2];
    float* out = (float*)d_out;

    __half *xr, *wqkvr, *woutr, *qkvp, *attp;
    cudaGetSymbolAddress((void**)&xr,    g_x);
    cudaGetSymbolAddress((void**)&wqkvr, g_wqkv);
    cudaGetSymbolAddress((void**)&woutr, g_wout);
    cudaGetSymbolAddress((void**)&qkvp,  g_qkv);
    cudaGetSymbolAddress((void**)&attp,  g_att);

    cudaFuncSetAttribute(gemm_f16<1>,
                         cudaFuncAttributeMaxDynamicSharedMemorySize, GEMM_SMEM);
    cudaFuncSetAttribute(gemm_f16<0>,
                         cudaFuncAttributeMaxDynamicSharedMemorySize, GEMM_SMEM);
    cudaFuncSetAttribute(flash_f16,
                         cudaFuncAttributeMaxDynamicSharedMemorySize, FL_SMEM);

    // 0) fp32 -> fp16 inputs, single launch
    {
        int na4 = S_LEN * DM / 4;
        int nb4 = QKV_N * DM / 4;
        int nc4 = DM * DM / 4;
        int ntot = na4 + nb4 + nc4;
        cvt_all_kernel<<<(ntot + 255) / 256, 256>>>(x, xr, na4, w_qkv, wqkvr, nb4,
                                                    w_out, woutr, nc4);
    }
    // 1) QKV projection (fp16 out; q scaled by 0.125*log2e)
    {
        dim3 grid(QKV_N / 128, S_LEN / 64);   // 24 x 64 = 1536 blocks
        gemm_f16<1><<<grid, 128, GEMM_SMEM>>>(xr, wqkvr, qkvp, S_LEN, QKV_N, DM);
    }
    // 2) Flash attention (fp16 out)
    {
        dim3 grid(S_LEN / 64, NH);
        flash_f16<<<grid, 128, FL_SMEM>>>(qkvp, attp);
    }
    // 3) Output projection (fp32 out)
    {
        dim3 grid(DM / 128, S_LEN / 64);      // 8 x 64 = 512 blocks
        gemm_f16<0><<<grid, 128, GEMM_SMEM>>>(attp, woutr, out, S_LEN, DM, DM);
    }
}

// round 15
// speedup vs baseline: 2.9781x; 1.0854x over previous
#include <cuda_runtime.h>
#include <cuda_fp16.h>
#include <cstdint>

// Problem constants
constexpr int S_LEN = 4096;
constexpr int DM    = 1024;
constexpr int NH    = 16;
constexpr int HD    = 64;
constexpr int QKV_N = 3 * DM;  // 3072

// q section scaled by 0.125*log2(e): softmax computed in exp2 domain.
constexpr float Q_SCALE = 0.125f * 1.4426950408889634f;

// Scratch device globals — fp16
__device__ __half g_x   [(size_t)S_LEN * DM];
__device__ __half g_wqkv[(size_t)QKV_N * DM];
__device__ __half g_wout[(size_t)DM * DM];
__device__ __half g_qkv [(size_t)S_LEN * QKV_N];
__device__ __half g_att [(size_t)S_LEN * DM];

// ---------------------------------------------------------------------------
// Helpers
// ---------------------------------------------------------------------------
__device__ __forceinline__ void cp_async16(void* smem_dst, const void* gmem_src) {
    uint32_t s = (uint32_t)__cvta_generic_to_shared(smem_dst);
    asm volatile("cp.async.cg.shared.global [%0], [%1], 16;" :: "r"(s), "l"(gmem_src));
}
__device__ __forceinline__ void cp_async16s(uint32_t smem_dst, const void* gmem_src) {
    asm volatile("cp.async.cg.shared.global [%0], [%1], 16;" :: "r"(smem_dst), "l"(gmem_src));
}
__device__ __forceinline__ void cp_commit() {
    asm volatile("cp.async.commit_group;");
}
template<int N>
__device__ __forceinline__ void cp_wait() {
    asm volatile("cp.async.wait_group %0;" :: "n"(N));
}
__device__ __forceinline__ uint32_t smem_u32(const void* p) {
    return (uint32_t)__cvta_generic_to_shared(p);
}
__device__ __forceinline__ float ex2(float x) {
    float y;
    asm("ex2.approx.ftz.f32 %0, %1;" : "=f"(y) : "f"(x));
    return y;
}
__device__ __forceinline__ uint32_t h2ex2(uint32_t x) {
    uint32_t y;
    asm("ex2.approx.f16x2 %0, %1;" : "=r"(y) : "r"(x));
    return y;
}
__device__ __forceinline__ void ldmx4(uint32_t r[4], uint32_t a) {
    asm volatile("ldmatrix.sync.aligned.m8n8.x4.shared.b16 {%0,%1,%2,%3}, [%4];"
                 : "=r"(r[0]), "=r"(r[1]), "=r"(r[2]), "=r"(r[3]) : "r"(a));
}
__device__ __forceinline__ void ldmx4t(uint32_t r[4], uint32_t a) {
    asm volatile("ldmatrix.sync.aligned.m8n8.x4.trans.shared.b16 {%0,%1,%2,%3}, [%4];"
                 : "=r"(r[0]), "=r"(r[1]), "=r"(r[2]), "=r"(r[3]) : "r"(a));
}
__device__ __forceinline__ void mma_f16(float c[4], const uint32_t a[4],
                                        uint32_t b0, uint32_t b1) {
    asm volatile(
        "mma.sync.aligned.m16n8k16.row.col.f32.f16.f16.f32 "
        "{%0,%1,%2,%3}, {%4,%5,%6,%7}, {%8,%9}, {%0,%1,%2,%3};"
        : "+f"(c[0]), "+f"(c[1]), "+f"(c[2]), "+f"(c[3])
        : "r"(a[0]), "r"(a[1]), "r"(a[2]), "r"(a[3]), "r"(b0), "r"(b1));
}
__device__ __forceinline__ uint32_t f2h2(float x, float y) {
    __half2 h = __floats2half2_rn(x, y);
    return *(uint32_t*)&h;
}
// XOR-seg swizzle for 128-byte rows: seg in [0,8), 16B units.
__device__ __forceinline__ uint32_t sw128(uint32_t row, uint32_t seg) {
    return row * 128 + (((seg ^ (row & 7)) & 7) * 16);
}

// ---------------------------------------------------------------------------
// fp32 -> fp16 conversion pre-pass: all three tensors, ONE launch
// ---------------------------------------------------------------------------
__global__ void cvt_all_kernel(const float* __restrict__ a, __half* __restrict__ oa, int na4,
                               const float* __restrict__ b, __half* __restrict__ ob, int nb4,
                               const float* __restrict__ c, __half* __restrict__ oc, int nc4) {
    int j = blockIdx.x * blockDim.x + threadIdx.x;
    const float* in; __half* out;
    if (j < na4) { in = a; out = oa; }
    else {
        j -= na4;
        if (j < nb4) { in = b; out = ob; }
        else {
            j -= nb4;
            if (j >= nc4) return;
            in = c; out = oc;
        }
    }
    float4 v = ((const float4*)in)[j];
    ((__half2*)out)[j * 2 + 0] = __floats2half2_rn(v.x, v.y);
    ((__half2*)out)[j * 2 + 1] = __floats2half2_rn(v.z, v.w);
}

// ---------------------------------------------------------------------------
// FP16 GEMM: C[M,N]=A[M,K]*B[N,K]^T, fp32 accum.
// Block 64x128, 128 threads / 4 warps, 32x64 warp tiles. K-chunk 64,
// 2-stage cp.async double buffer, one barrier per 64-K.
// MODE 1: fp16 out; q cols (col<DM) scaled by Q_SCALE.  MODE 0: fp32 out.
// ---------------------------------------------------------------------------
constexpr int G_STRIDE  = 144;
constexpr int GA_STAGE  = 64 * G_STRIDE;
constexpr int GB_STAGE  = 128 * G_STRIDE;
constexpr int GEMM_SMEM = 2 * (GA_STAGE + GB_STAGE);  // 55296 B

template<int MODE>
__global__ __launch_bounds__(128) void gemm_f16(
    const __half* __restrict__ A, const __half* __restrict__ B,
    void* __restrict__ Cv, int M, int N, int K)
{
    extern __shared__ char sm[];
    char* AsBase = sm;
    char* BsBase = sm + 2 * GA_STAGE;

    const int tid  = threadIdx.x;
    const int lane = tid & 31;
    const int wid  = tid >> 5;
    const int wm   = (wid >> 1) * 32;
    const int wn   = (wid & 1) * 64;
    const int m0   = blockIdx.y * 64;
    const int n0   = blockIdx.x * 128;
    const int NI   = K / 64;

    const int grp = lane >> 3, rw = lane & 7;
    const int a_row = (grp & 1) * 8 + rw;
    const int a_byt = (grp >> 1) * 16;
    const int b_row = (grp >> 1) * 8 + rw;
    const int b_byt = (grp & 1) * 16;

    auto issue_tile = [&](int it, int buf) {
        const char* Ag = (const char*)(A + (size_t)m0 * K + it * 64);
        const char* Bg = (const char*)(B + (size_t)n0 * K + it * 64);
        char* As = AsBase + buf * GA_STAGE;
        char* Bs = BsBase + buf * GB_STAGE;
#pragma unroll
        for (int p = 0; p < 4; ++p) {
            int idx = tid + p * 128;
            int row = idx >> 3;
            int seg = (idx & 7) * 16;
            cp_async16(As + row * G_STRIDE + seg, Ag + (size_t)row * K * 2 + seg);
        }
#pragma unroll
        for (int p = 0; p < 8; ++p) {
            int idx = tid + p * 128;
            int row = idx >> 3;
            int seg = (idx & 7) * 16;
            cp_async16(Bs + row * G_STRIDE + seg, Bg + (size_t)row * K * 2 + seg);
        }
        cp_commit();
    };

    float acc[2][8][4];
#pragma unroll
    for (int i = 0; i < 2; ++i)
#pragma unroll
        for (int j = 0; j < 8; ++j)
#pragma unroll
            for (int c = 0; c < 4; ++c) acc[i][j][c] = 0.f;

    issue_tile(0, 0);

    for (int it = 0; it < NI; ++it) {
        cp_wait<0>();
        __syncthreads();
        if (it + 1 < NI) issue_tile(it + 1, (it + 1) & 1);

        const uint32_t a_base = smem_u32(AsBase + (it & 1) * GA_STAGE);
        const uint32_t b_base = smem_u32(BsBase + (it & 1) * GB_STAGE);

#pragma unroll
        for (int ks = 0; ks < 4; ++ks) {
            uint32_t a[2][4], b[4][4];
#pragma unroll
            for (int mt = 0; mt < 2; ++mt)
                ldmx4(a[mt], a_base + (wm + mt * 16 + a_row) * G_STRIDE
                              + ks * 32 + a_byt);
#pragma unroll
            for (int u = 0; u < 4; ++u)
                ldmx4(b[u], b_base + (wn + u * 16 + b_row) * G_STRIDE
                             + ks * 32 + b_byt);
#pragma unroll
            for (int mt = 0; mt < 2; ++mt)
#pragma unroll
                for (int u = 0; u < 4; ++u) {
                    mma_f16(acc[mt][2 * u],     a[mt], b[u][0], b[u][1]);
                    mma_f16(acc[mt][2 * u + 1], a[mt], b[u][2], b[u][3]);
                }
        }
    }

#pragma unroll
    for (int mt = 0; mt < 2; ++mt) {
#pragma unroll
        for (int nt = 0; nt < 8; ++nt) {
            int row = m0 + wm + mt * 16 + (lane >> 2);
            int col = n0 + wn + nt * 8 + 2 * (lane & 3);
            if (MODE == 1) {
                __half* C = (__half*)Cv;
                float s = (col < DM) ? Q_SCALE : 1.0f;
                *(__half2*)&C[(size_t)row * N + col] =
                    __floats2half2_rn(acc[mt][nt][0] * s, acc[mt][nt][1] * s);
                *(__half2*)&C[(size_t)(row + 8) * N + col] =
                    __floats2half2_rn(acc[mt][nt][2] * s, acc[mt][nt][3] * s);
            } else {
                float* C = (float*)Cv;
                *(float2*)&C[(size_t)row * N + col] =
                    make_float2(acc[mt][nt][0], acc[mt][nt][1]);
                *(float2*)&C[(size_t)(row + 8) * N + col] =
                    make_float2(acc[mt][nt][2], acc[mt][nt][3]);
            }
        }
    }
}

// ---------------------------------------------------------------------------
// Flash attention, fp16 mma + ldmatrix, 128-col KV pairs, f16x2 exp2 path.
// Smem rows exact 128 B with XOR-seg swizzle -> 72 KB total ->
// 3 blocks/SM (12 warps). __launch_bounds__(128,3) caps regs at 168.
// ---------------------------------------------------------------------------
constexpr int F_TILE   = 64 * 128;             // 8192 B (64 rows x 128 B)
constexpr int F_PAIR   = 2 * F_TILE;           // 16384 B
constexpr int FL_SMEM  = F_TILE + 4 * F_PAIR;  // 73728 B

__global__ __launch_bounds__(128, 3) void flash_f16(
    const __half* __restrict__ qkv, __half* __restrict__ out)
{
    extern __shared__ char fsm[];
    const uint32_t q_base = smem_u32(fsm);
    const uint32_t k_base0 = q_base + F_TILE;
    const uint32_t v_base0 = q_base + F_TILE + 2 * F_PAIR;

    const int tid  = threadIdx.x;
    const int lane = tid & 31;
    const int w    = tid >> 5;
    const int h    = blockIdx.y;
    const int qt   = (int)gridDim.x - 1 - (int)blockIdx.x;  // heavy first
    const int q0   = qt * 64;
    const int pmax = qt >> 1;

    const int grp = lane >> 3, rw = lane & 7;
    const int q_row = (grp & 1) * 8 + rw;   // + w*16
    const int q_seg = grp >> 1;             // + ks*2
    const int k_row = (grp >> 1) * 8 + rw;  // + u*16
    const int k_seg = grp & 1;              // + ks*2
    const int v_row = (grp & 1) * 8 + rw;   // + ks*16
    const int v_seg = grp >> 1;             // + u*2

    const char* qg = (const char*)(qkv + (size_t)q0 * QKV_N + h * HD);

    auto issue_pair = [&](int p, int buf) {
        uint32_t Ks = k_base0 + buf * F_PAIR;
        uint32_t Vs = v_base0 + buf * F_PAIR;
#pragma unroll
        for (int half = 0; half < 2; ++half) {
            int tile = 2 * p + half;
            if (tile > S_LEN / 64 - 1) tile = S_LEN / 64 - 1;
            const char* kg = (const char*)(qkv + (size_t)(tile * 64) * QKV_N + DM + h * HD);
            const char* vg = kg + DM * 2;
#pragma unroll
            for (int pp = 0; pp < 4; ++pp) {
                int idx = tid + pp * 128;     // 0..511 (64 rows x 8 segs)
                int row = idx >> 3;
                int seg = idx & 7;
                uint32_t off = sw128(half * 64 + row, seg);
                cp_async16s(Ks + off, kg + (size_t)row * QKV_N * 2 + seg * 16);
                cp_async16s(Vs + off, vg + (size_t)row * QKV_N * 2 + seg * 16);
            }
        }
        cp_commit();
    };

    // Prologue: Q then pair 0
    {
#pragma unroll
        for (int pp = 0; pp < 4; ++pp) {
            int idx = tid + pp * 128;
            int row = idx >> 3;
            int seg = idx & 7;
            cp_async16s(q_base + sw128(row, seg),
                        qg + (size_t)row * QKV_N * 2 + seg * 16);
        }
        cp_commit();
    }
    issue_pair(0, 0);

    const int r  = (lane >> 2);
    const int qr = w * 16 + r;
    uint32_t Qf[4][4];
    float m_i[2] = {-1e30f, -1e30f};
    float l_i[2] = {0.f, 0.f};
    float oacc[8][4];
#pragma unroll
    for (int n = 0; n < 8; ++n)
#pragma unroll
        for (int c = 0; c < 4; ++c) oacc[n][c] = 0.f;

    for (int p = 0; p <= pmax; ++p) {
        cp_wait<0>();
        __syncthreads();
        if (p + 1 <= pmax) issue_pair(p + 1, (p + 1) & 1);

        if (p == 0) {
#pragma unroll
            for (int ks = 0; ks < 4; ++ks)
                ldmx4(Qf[ks], q_base + sw128(w * 16 + q_row, ks * 2 + q_seg));
        }

        const uint32_t k_base = k_base0 + (p & 1) * F_PAIR;
        const uint32_t v_base = v_base0 + (p & 1) * F_PAIR;

        // S = Q K^T over 128 cols
        float sacc[16][4];
#pragma unroll
        for (int n = 0; n < 16; ++n)
#pragma unroll
            for (int c = 0; c < 4; ++c) sacc[n][c] = 0.f;

#pragma unroll
        for (int ks = 0; ks < 4; ++ks) {
#pragma unroll
            for (int u = 0; u < 8; ++u) {
                uint32_t b[4];
                ldmx4(b, k_base + sw128(u * 16 + k_row, ks * 2 + k_seg));
                mma_f16(sacc[2 * u],     Qf[ks], b[0], b[1]);
                mma_f16(sacc[2 * u + 1], Qf[ks], b[2], b[3]);
            }
        }

        // Causal mask — only the last pair straddles/exceeds the diagonal
        if (p == pmax) {
#pragma unroll
            for (int nt = 0; nt < 16; ++nt) {
#pragma unroll
                for (int c = 0; c < 4; ++c) {
                    int col_g = p * 128 + nt * 8 + 2 * (lane & 3) + (c & 1);
                    int row_g = q0 + qr + (c >> 1) * 8;
                    if (col_g > row_g) sacc[nt][c] = -1e30f;
                }
            }
        }

        // Online softmax (exp2 domain), P via ex2.approx.f16x2.
        float alpha[2];
        uint32_t pa[8][4];
#pragma unroll
        for (int half = 0; half < 2; ++half) {
            float mx = -1e30f;
#pragma unroll
            for (int nt = 0; nt < 16; ++nt) {
                mx = fmaxf(mx, sacc[nt][half * 2]);
                mx = fmaxf(mx, sacc[nt][half * 2 + 1]);
            }
            mx = fmaxf(mx, __shfl_xor_sync(0xffffffffu, mx, 1, 4));
            mx = fmaxf(mx, __shfl_xor_sync(0xffffffffu, mx, 2, 4));
            float mnew = fmaxf(m_i[half], mx);
            alpha[half] = ex2(m_i[half] - mnew);
            m_i[half] = mnew;
            float rs = 0.f;
#pragma unroll
            for (int nt = 0; nt < 16; ++nt) {
                uint32_t hp = h2ex2(f2h2(sacc[nt][half * 2]     - mnew,
                                         sacc[nt][half * 2 + 1] - mnew));
                pa[nt >> 1][(nt & 1) * 2 + half] = hp;
                float2 f = __half22float2(*(__half2*)&hp);
                rs += f.x + f.y;
            }
            rs += __shfl_xor_sync(0xffffffffu, rs, 1, 4);
            rs += __shfl_xor_sync(0xffffffffu, rs, 2, 4);
            l_i[half] = l_i[half] * alpha[half] + rs;
        }

#pragma unroll
        for (int nt = 0; nt < 8; ++nt) {
            oacc[nt][0] *= alpha[0]; oacc[nt][1] *= alpha[0];
            oacc[nt][2] *= alpha[1]; oacc[nt][3] *= alpha[1];
        }

        // O += P V  (V via ldmatrix.trans)
#pragma unroll
        for (int ks = 0; ks < 8; ++ks) {
#pragma unroll
            for (int u = 0; u < 4; ++u) {
                uint32_t b[4];
                ldmx4t(b, v_base + sw128(ks * 16 + v_row, u * 2 + v_seg));
                mma_f16(oacc[2 * u],     pa[ks], b[0], b[1]);
                mma_f16(oacc[2 * u + 1], pa[ks], b[2], b[3]);
            }
        }
    }

    // Epilogue
    float inv0 = 1.f / l_i[0];
    float inv1 = 1.f / l_i[1];
#pragma unroll
    for (int nt = 0; nt < 8; ++nt) {
        int col = h * HD + nt * 8 + 2 * (lane & 3);
        int row = q0 + qr;
        *(__half2*)&out[(size_t)row * DM + col] =
            __floats2half2_rn(oacc[nt][0] * inv0, oacc[nt][1] * inv0);
        *(__half2*)&out[(size_t)(row + 8) * DM + col] =
            __floats2half2_rn(oacc[nt][2] * inv1, oacc[nt][3] * inv1);
    }
}

// ---------------------------------------------------------------------------
// Launch
// ---------------------------------------------------------------------------
extern "C" void kernel_launch(void* const* d_in, const int* in_sizes, int n_in,
                              void* d_out, int out_size)
{
    const float* x     = (const float*)d_in[0];
    const float* w_qkv = (const float*)d_in[1];
    const float* w_out = (const float*)d_in[2];
    float* out = (float*)d_out;

    __half *xr, *wqkvr, *woutr, *qkvp, *attp;
    cudaGetSymbolAddress((void**)&xr,    g_x);
    cudaGetSymbolAddress((void**)&wqkvr, g_wqkv);
    cudaGetSymbolAddress((void**)&woutr, g_wout);
    cudaGetSymbolAddress((void**)&qkvp,  g_qkv);
    cudaGetSymbolAddress((void**)&attp,  g_att);

    cudaFuncSetAttribute(gemm_f16<1>,
                         cudaFuncAttributeMaxDynamicSharedMemorySize, GEMM_SMEM);
    cudaFuncSetAttribute(gemm_f16<0>,
                         cudaFuncAttributeMaxDynamicSharedMemorySize, GEMM_SMEM);
    cudaFuncSetAttribute(flash_f16,
                         cudaFuncAttributeMaxDynamicSharedMemorySize, FL_SMEM);

    // 0) fp32 -> fp16 inputs, single launch
    {
        int na4 = S_LEN * DM / 4;
        int nb4 = QKV_N * DM / 4;
        int nc4 = DM * DM / 4;
        int ntot = na4 + nb4 + nc4;
        cvt_all_kernel<<<(ntot + 255) / 256, 256>>>(x, xr, na4, w_qkv, wqkvr, nb4,
                                                    w_out, woutr, nc4);
    }
    // 1) QKV projection (fp16 out; q scaled by 0.125*log2e)
    {
        dim3 grid(QKV_N / 128, S_LEN / 64);
        gemm_f16<1><<<grid, 128, GEMM_SMEM>>>(xr, wqkvr, qkvp, S_LEN, QKV_N, DM);
    }
    // 2) Flash attention (fp16 out)
    {
        dim3 grid(S_LEN / 64, NH);
        flash_f16<<<grid, 128, FL_SMEM>>>(qkvp, attp);
    }
    // 3) Output projection (fp32 out)
    {
        dim3 grid(DM / 128, S_LEN / 64);
        gemm_f16<0><<<grid, 128, GEMM_SMEM>>>(attp, woutr, out, S_LEN, DM, DM);
    }
}